// round 1
// baseline (speedup 1.0000x reference)
#include <cuda_runtime.h>
#include <cuda_bf16.h>

#define N_BATCH 4
#define C_DIM   512
#define T_DIM   4096
#define NTOK    (N_BATCH * T_DIM)   // 16384
#define H_HEADS 8
#define DH      64
#define CHUNK_SZ 64
#define NEG_INF (-1e9f)

// ---------------- scratch (device globals; no allocation allowed) ------------
__device__ float g_WtIn[C_DIM * 3 * C_DIM];   // [c][co3]  512 x 1536
__device__ float g_WtOut[C_DIM * C_DIM];      // [c][co]   512 x 512
__device__ float g_QP[(size_t)NTOK * C_DIM];  // [g][co]
__device__ float g_KP[(size_t)NTOK * C_DIM];
__device__ float g_VP[(size_t)NTOK * C_DIM];
__device__ float g_AOt[(size_t)C_DIM * NTOK]; // [co][g]  (transposed attn out)

// ---------------- transpose: in[rows][cols] -> out[cols][rows] ---------------
__global__ void transpose_kernel(const float* __restrict__ in,
                                 float* __restrict__ out, int rows, int cols)
{
    __shared__ float tile[32][33];
    int bx = blockIdx.x * 32, by = blockIdx.y * 32;
    int x = bx + threadIdx.x;
    #pragma unroll
    for (int j = 0; j < 32; j += 8) {
        int y = by + threadIdx.y + j;
        if (y < rows && x < cols) tile[threadIdx.y + j][threadIdx.x] = in[(size_t)y * cols + x];
    }
    __syncthreads();
    int x2 = by + threadIdx.x;
    #pragma unroll
    for (int j = 0; j < 32; j += 8) {
        int y2 = bx + threadIdx.y + j;
        if (y2 < cols && x2 < rows) out[(size_t)y2 * rows + x2] = tile[threadIdx.x][threadIdx.y + j];
    }
}

// ---------------- SGEMM: projections --------------------------------------
// C[g][co] = sum_c A[n][c][t] * B[c][co] + bias[co]
// A: input tensor [N][C][T] (k-stride = T, contiguous in token within batch)
// B: Wt section base, ldb = 1536.  Cout: [g][512].
__global__ void __launch_bounds__(256) gemm_proj(
    const float* __restrict__ A, const float* __restrict__ B,
    const float* __restrict__ bias, float* __restrict__ Cout, int ldb)
{
    __shared__ float As[8][128];
    __shared__ float Bs[8][128];

    int g0 = blockIdx.x * 128;
    int bn = blockIdx.y;                 // 0..3
    int n  = g0 / T_DIM;
    int t0 = g0 % T_DIM;
    const float* Aptr = A + (size_t)n * C_DIM * T_DIM + t0;
    const float* Bptr = B + bn * 128;

    int tid = threadIdx.x;
    int lk  = tid >> 5;            // 0..7
    int lm  = (tid & 31) * 4;      // 0..124
    int ty  = tid >> 4, tx = tid & 15;

    float acc[8][8];
    #pragma unroll
    for (int i = 0; i < 8; i++)
        #pragma unroll
        for (int j = 0; j < 8; j++) acc[i][j] = 0.f;

    for (int kt = 0; kt < C_DIM; kt += 8) {
        *(float4*)(&As[lk][lm]) = *(const float4*)(Aptr + (size_t)(kt + lk) * T_DIM + lm);
        *(float4*)(&Bs[lk][lm]) = *(const float4*)(Bptr + (size_t)(kt + lk) * ldb + lm);
        __syncthreads();
        #pragma unroll
        for (int kk = 0; kk < 8; kk++) {
            float a[8], b[8];
            *(float4*)(a)     = *(const float4*)(&As[kk][ty * 4]);
            *(float4*)(a + 4) = *(const float4*)(&As[kk][64 + ty * 4]);
            *(float4*)(b)     = *(const float4*)(&Bs[kk][tx * 4]);
            *(float4*)(b + 4) = *(const float4*)(&Bs[kk][64 + tx * 4]);
            #pragma unroll
            for (int i = 0; i < 8; i++)
                #pragma unroll
                for (int j = 0; j < 8; j++) acc[i][j] = fmaf(a[i], b[j], acc[i][j]);
        }
        __syncthreads();
    }

    int cbase = bn * 128 + tx * 4;
    float bb0[4], bb1[4];
    #pragma unroll
    for (int j = 0; j < 4; j++) { bb0[j] = bias[cbase + j]; bb1[j] = bias[cbase + 64 + j]; }
    #pragma unroll
    for (int ih = 0; ih < 2; ih++) {
        #pragma unroll
        for (int i = 0; i < 4; i++) {
            int m = ih * 64 + ty * 4 + i;
            size_t rowoff = (size_t)(g0 + m) * C_DIM;
            float4 o0, o1;
            o0.x = acc[ih*4+i][0] + bb0[0]; o0.y = acc[ih*4+i][1] + bb0[1];
            o0.z = acc[ih*4+i][2] + bb0[2]; o0.w = acc[ih*4+i][3] + bb0[3];
            o1.x = acc[ih*4+i][4] + bb1[0]; o1.y = acc[ih*4+i][5] + bb1[1];
            o1.z = acc[ih*4+i][6] + bb1[2]; o1.w = acc[ih*4+i][7] + bb1[3];
            *(float4*)(Cout + rowoff + cbase)      = o0;
            *(float4*)(Cout + rowoff + cbase + 64) = o1;
        }
    }
}

// ---------------- attention: one block per (chunk, head) --------------------
__global__ void __launch_bounds__(256) attn_kernel(const float* __restrict__ masks)
{
    __shared__ float bufA[64 * 64];  // Q^T [d][q]   -> then S [q][k]
    __shared__ float bufB[64 * 64];  // K^T [d][k]   -> then P^T [k][q]
    __shared__ float bufC[64 * 64];  // V   [k][d]

    int cb = blockIdx.x;          // chunk index over all batches: g0 = cb*64
    int h  = blockIdx.y;
    int g0 = cb * CHUNK_SZ;
    int n  = g0 / T_DIM;
    int t0 = g0 % T_DIM;

    int tid  = threadIdx.x;
    int qrow = tid >> 2;              // 0..63
    int dseg = (tid & 3) * 16;        // 0,16,32,48

    const float* qp = g_QP + (size_t)(g0 + qrow) * C_DIM + h * DH + dseg;
    const float* kp = g_KP + (size_t)(g0 + qrow) * C_DIM + h * DH + dseg;
    const float* vp = g_VP + (size_t)(g0 + qrow) * C_DIM + h * DH + dseg;

    #pragma unroll
    for (int i = 0; i < 4; i++) {
        int d = dseg + i * 4;
        float4 tq = *(const float4*)(qp + i * 4);
        bufA[(d+0)*64 + qrow] = tq.x; bufA[(d+1)*64 + qrow] = tq.y;
        bufA[(d+2)*64 + qrow] = tq.z; bufA[(d+3)*64 + qrow] = tq.w;
        float4 tk = *(const float4*)(kp + i * 4);
        bufB[(d+0)*64 + qrow] = tk.x; bufB[(d+1)*64 + qrow] = tk.y;
        bufB[(d+2)*64 + qrow] = tk.z; bufB[(d+3)*64 + qrow] = tk.w;
        float4 tv = *(const float4*)(vp + i * 4);
        *(float4*)(&bufC[qrow * 64 + d]) = tv;
    }
    __syncthreads();

    int ty = tid >> 4, tx = tid & 15;

    // S = Q K^T   (4x4 per thread)
    float s[4][4];
    #pragma unroll
    for (int i = 0; i < 4; i++)
        #pragma unroll
        for (int j = 0; j < 4; j++) s[i][j] = 0.f;
    #pragma unroll 8
    for (int d = 0; d < 64; d++) {
        float4 a = *(const float4*)(&bufA[d * 64 + ty * 4]);
        float4 b = *(const float4*)(&bufB[d * 64 + tx * 4]);
        float av[4] = {a.x, a.y, a.z, a.w};
        float bv[4] = {b.x, b.y, b.z, b.w};
        #pragma unroll
        for (int i = 0; i < 4; i++)
            #pragma unroll
            for (int j = 0; j < 4; j++) s[i][j] = fmaf(av[i], bv[j], s[i][j]);
    }
    __syncthreads();

    // write S into bufA as [q][k]
    #pragma unroll
    for (int i = 0; i < 4; i++) {
        float4 sv = make_float4(s[i][0], s[i][1], s[i][2], s[i][3]);
        *(float4*)(&bufA[(ty * 4 + i) * 64 + tx * 4]) = sv;
    }
    __syncthreads();

    // softmax: warp per row group; write P^T into bufB
    int warp = tid >> 5, lane = tid & 31;
    const float scale = 0.125f;  // 1/sqrt(64)
    const float* mrow = masks + (size_t)n * T_DIM + t0;
    float mk1 = (mrow[lane]      > 0.f) ? 0.f : NEG_INF;
    float mk2 = (mrow[lane + 32] > 0.f) ? 0.f : NEG_INF;
    for (int r = warp; r < 64; r += 8) {
        float v1 = bufA[r * 64 + lane]      * scale + mk1;
        float v2 = bufA[r * 64 + lane + 32] * scale + mk2;
        float mx = fmaxf(v1, v2);
        #pragma unroll
        for (int o = 16; o; o >>= 1) mx = fmaxf(mx, __shfl_xor_sync(0xffffffffu, mx, o));
        float e1 = __expf(v1 - mx);
        float e2 = __expf(v2 - mx);
        float sm = e1 + e2;
        #pragma unroll
        for (int o = 16; o; o >>= 1) sm += __shfl_xor_sync(0xffffffffu, sm, o);
        float inv = 1.f / sm;
        bufB[lane * 64 + r]        = e1 * inv;
        bufB[(lane + 32) * 64 + r] = e2 * inv;
    }
    __syncthreads();

    // O = P V  (bufB = P^T [k][q], bufC = V [k][d])
    float o[4][4];
    #pragma unroll
    for (int i = 0; i < 4; i++)
        #pragma unroll
        for (int j = 0; j < 4; j++) o[i][j] = 0.f;
    #pragma unroll 8
    for (int k = 0; k < 64; k++) {
        float4 a = *(const float4*)(&bufB[k * 64 + ty * 4]);
        float4 b = *(const float4*)(&bufC[k * 64 + tx * 4]);
        float av[4] = {a.x, a.y, a.z, a.w};
        float bv[4] = {b.x, b.y, b.z, b.w};
        #pragma unroll
        for (int i = 0; i < 4; i++)
            #pragma unroll
            for (int j = 0; j < 4; j++) o[i][j] = fmaf(av[i], bv[j], o[i][j]);
    }

    // write transposed attention output: g_AOt[co][g]
    #pragma unroll
    for (int j = 0; j < 4; j++) {
        int co = h * DH + tx * 4 + j;
        float4 ov = make_float4(o[0][j], o[1][j], o[2][j], o[3][j]);
        *(float4*)(&g_AOt[(size_t)co * NTOK + g0 + ty * 4]) = ov;
    }
}

// ---------------- SGEMM: out-projection + mask + residual -------------------
// out[n][co][t] = (sum_c AOt[c][g] * WtOut[c][co] + b_out[co]) * mask[n][t] + x[n][co][t]
__global__ void __launch_bounds__(256) gemm_out(
    const float* __restrict__ B, const float* __restrict__ bias,
    const float* __restrict__ masks, const float* __restrict__ x,
    float* __restrict__ out)
{
    __shared__ float As[8][128];
    __shared__ float Bs[8][128];

    int g0 = blockIdx.x * 128;
    int bn = blockIdx.y;
    int n  = g0 / T_DIM;
    int t0 = g0 % T_DIM;
    const float* Bptr = B + bn * 128;

    int tid = threadIdx.x;
    int lk  = tid >> 5;
    int lm  = (tid & 31) * 4;
    int ty  = tid >> 4, tx = tid & 15;

    float acc[8][8];
    #pragma unroll
    for (int i = 0; i < 8; i++)
        #pragma unroll
        for (int j = 0; j < 8; j++) acc[i][j] = 0.f;

    for (int kt = 0; kt < C_DIM; kt += 8) {
        *(float4*)(&As[lk][lm]) = *(const float4*)(g_AOt + (size_t)(kt + lk) * NTOK + g0 + lm);
        *(float4*)(&Bs[lk][lm]) = *(const float4*)(Bptr + (size_t)(kt + lk) * C_DIM + lm);
        __syncthreads();
        #pragma unroll
        for (int kk = 0; kk < 8; kk++) {
            float a[8], b[8];
            *(float4*)(a)     = *(const float4*)(&As[kk][ty * 4]);
            *(float4*)(a + 4) = *(const float4*)(&As[kk][64 + ty * 4]);
            *(float4*)(b)     = *(const float4*)(&Bs[kk][tx * 4]);
            *(float4*)(b + 4) = *(const float4*)(&Bs[kk][64 + tx * 4]);
            #pragma unroll
            for (int i = 0; i < 8; i++)
                #pragma unroll
                for (int j = 0; j < 8; j++) acc[i][j] = fmaf(a[i], b[j], acc[i][j]);
        }
        __syncthreads();
    }

    // epilogue: channel-major output with mask and residual
    #pragma unroll
    for (int jh = 0; jh < 2; jh++) {
        #pragma unroll
        for (int j = 0; j < 4; j++) {
            int co = bn * 128 + jh * 64 + tx * 4 + j;
            float bb = bias[co];
            #pragma unroll
            for (int ih = 0; ih < 2; ih++) {
                int mloc = ih * 64 + ty * 4;
                int t = t0 + mloc;
                size_t oidx = ((size_t)(n * C_DIM + co)) * T_DIM + t;
                float4 xm = *(const float4*)(x + oidx);
                float4 mk = *(const float4*)(masks + (size_t)n * T_DIM + t);
                float4 r;
                r.x = (acc[ih*4+0][jh*4+j] + bb) * mk.x + xm.x;
                r.y = (acc[ih*4+1][jh*4+j] + bb) * mk.y + xm.y;
                r.z = (acc[ih*4+2][jh*4+j] + bb) * mk.z + xm.z;
                r.w = (acc[ih*4+3][jh*4+j] + bb) * mk.w + xm.w;
                *(float4*)(out + oidx) = r;
            }
        }
    }
}

// ---------------- InstanceNorm1d over T per (n,c) row ----------------------
__global__ void __launch_bounds__(256) inorm_kernel(float* __restrict__ out)
{
    __shared__ float red[18];
    int row = blockIdx.x;                 // n*C + c, 2048 rows
    float* p = out + (size_t)row * T_DIM;
    int tid = threadIdx.x;

    float4 v[4];
    float s = 0.f, s2 = 0.f;
    #pragma unroll
    for (int i = 0; i < 4; i++) {
        v[i] = *(const float4*)(p + i * 1024 + tid * 4);
        s  += v[i].x + v[i].y + v[i].z + v[i].w;
        s2 += v[i].x * v[i].x + v[i].y * v[i].y + v[i].z * v[i].z + v[i].w * v[i].w;
    }
    #pragma unroll
    for (int o = 16; o; o >>= 1) {
        s  += __shfl_xor_sync(0xffffffffu, s,  o);
        s2 += __shfl_xor_sync(0xffffffffu, s2, o);
    }
    int warp = tid >> 5, lane = tid & 31;
    if (lane == 0) { red[warp] = s; red[8 + warp] = s2; }
    __syncthreads();
    if (warp == 0) {
        float a  = (lane < 8) ? red[lane]     : 0.f;
        float a2 = (lane < 8) ? red[8 + lane] : 0.f;
        #pragma unroll
        for (int o = 4; o; o >>= 1) {
            a  += __shfl_xor_sync(0xffffffffu, a,  o);
            a2 += __shfl_xor_sync(0xffffffffu, a2, o);
        }
        if (lane == 0) { red[16] = a; red[17] = a2; }
    }
    __syncthreads();
    float mu  = red[16] * (1.f / T_DIM);
    float var = red[17] * (1.f / T_DIM) - mu * mu;
    float rs  = rsqrtf(var + 1e-5f);
    #pragma unroll
    for (int i = 0; i < 4; i++) {
        float4 r;
        r.x = (v[i].x - mu) * rs; r.y = (v[i].y - mu) * rs;
        r.z = (v[i].z - mu) * rs; r.w = (v[i].w - mu) * rs;
        *(float4*)(p + i * 1024 + tid * 4) = r;
    }
}

// ---------------- launch ----------------------------------------------------
extern "C" void kernel_launch(void* const* d_in, const int* in_sizes, int n_in,
                              void* d_out, int out_size)
{
    const float* x     = (const float*)d_in[0];
    const float* q     = (const float*)d_in[1];
    const float* k     = (const float*)d_in[2];
    const float* v     = (const float*)d_in[3];
    const float* masks = (const float*)d_in[4];
    const float* W_in  = (const float*)d_in[5];
    const float* b_in  = (const float*)d_in[6];
    const float* W_out = (const float*)d_in[7];
    const float* b_out = (const float*)d_in[8];
    float* out = (float*)d_out;

    float *WtIn, *WtOut, *QP, *KP, *VP;
    cudaGetSymbolAddress((void**)&WtIn,  g_WtIn);
    cudaGetSymbolAddress((void**)&WtOut, g_WtOut);
    cudaGetSymbolAddress((void**)&QP,    g_QP);
    cudaGetSymbolAddress((void**)&KP,    g_KP);
    cudaGetSymbolAddress((void**)&VP,    g_VP);

    // W_in: [1536,512] -> [512,1536] ; W_out: [512,512] -> [512,512]
    transpose_kernel<<<dim3(512 / 32, 1536 / 32), dim3(32, 8)>>>(W_in,  WtIn,  1536, 512);
    transpose_kernel<<<dim3(512 / 32,  512 / 32), dim3(32, 8)>>>(W_out, WtOut,  512, 512);

    dim3 gg(NTOK / 128, C_DIM / 128);
    gemm_proj<<<gg, 256>>>(q, WtIn + 0,    b_in + 0,    QP, 3 * C_DIM);
    gemm_proj<<<gg, 256>>>(k, WtIn + 512,  b_in + 512,  KP, 3 * C_DIM);
    gemm_proj<<<gg, 256>>>(v, WtIn + 1024, b_in + 1024, VP, 3 * C_DIM);

    attn_kernel<<<dim3(NTOK / CHUNK_SZ, H_HEADS), 256>>>(masks);

    gemm_out<<<gg, 256>>>(WtOut, b_out, masks, x, out);

    inorm_kernel<<<N_BATCH * C_DIM, 256>>>(out);
}

// round 2
// speedup vs baseline: 2.1076x; 2.1076x over previous
#include <cuda_runtime.h>
#include <cuda_bf16.h>
#include <cstdint>

#define N_BATCH 4
#define C_DIM   512
#define T_DIM   4096
#define NTOK    (N_BATCH * T_DIM)   // 16384
#define H_HEADS 8
#define DH      64
#define CHUNK_SZ 64
#define NEG_INF (-1e9f)

// GEMM tiling
#define BM 128
#define BN 128
#define BK 32
#define APITCH 132                    // float2 pitch per kc-row
#define STAGE_U32 (16 * APITCH * 2)   // one operand buffer (A or B) in u32: 4224
#define BUF_U32   (2 * STAGE_U32)     // A+B one stage: 8448
#define SMEM_U32  (2 * BUF_U32)       // double buffered: 16896 u32 = 67584 B

// ---------------- scratch (device globals; no allocation allowed) ------------
__device__ float g_WtIn[C_DIM * 3 * C_DIM];   // [c][co3]  512 x 1536
__device__ float g_WtOut[C_DIM * C_DIM];      // [c][co]   512 x 512
__device__ float g_QP[(size_t)NTOK * C_DIM];  // [g][co]
__device__ float g_KP[(size_t)NTOK * C_DIM];
__device__ float g_VP[(size_t)NTOK * C_DIM];
__device__ float g_AOt[(size_t)C_DIM * NTOK]; // [co][g]  (transposed attn out)

// ---------------- helpers ---------------------------------------------------
__device__ __forceinline__ uint32_t f2tf32(float x) {
    uint32_t u;
    asm("cvt.rna.tf32.f32 %0, %1;" : "=r"(u) : "f"(x));
    return u;
}

__device__ __forceinline__ void mma_tf32(float* c,
                                         uint32_t a0, uint32_t a1, uint32_t a2, uint32_t a3,
                                         uint32_t b0, uint32_t b1) {
    asm volatile(
        "mma.sync.aligned.m16n8k8.row.col.f32.tf32.tf32.f32 "
        "{%0,%1,%2,%3}, {%4,%5,%6,%7}, {%8,%9}, {%0,%1,%2,%3};\n"
        : "+f"(c[0]), "+f"(c[1]), "+f"(c[2]), "+f"(c[3])
        : "r"(a0), "r"(a1), "r"(a2), "r"(a3), "r"(b0), "r"(b1));
}

// load 16 floats of one operand tile (BKxBM) from global into regs
// row kloc = (tid>>5) + 8*i, col m = (tid&31) + 32*j
__device__ __forceinline__ void ldg_tile(const float* __restrict__ base, size_t ld,
                                         int kt, int tid, float r[16]) {
    int kr = tid >> 5;
    int lm = tid & 31;
    #pragma unroll
    for (int i = 0; i < 4; i++) {
        const float* p = base + (size_t)(kt * BK + kr + 8 * i) * ld + lm;
        #pragma unroll
        for (int j = 0; j < 4; j++) r[i * 4 + j] = p[32 * j];
    }
}

// convert + store 16 values into interleaved smem stage
__device__ __forceinline__ void sts_tile(uint32_t* __restrict__ s, int tid, const float r[16]) {
    int kr = tid >> 5;
    int lm = tid & 31;
    #pragma unroll
    for (int i = 0; i < 4; i++) {
        int kloc = kr + 8 * i;
        int ks = kloc >> 3, kc = kloc & 3, kh = (kloc >> 2) & 1;
        uint32_t* q = s + ((ks * 4 + kc) * APITCH) * 2 + kh;
        #pragma unroll
        for (int j = 0; j < 4; j++) q[(lm + 32 * j) * 2] = f2tf32(r[i * 4 + j]);
    }
}

// ---------------- transpose: in[rows][cols] -> out[cols][rows] ---------------
__global__ void transpose_kernel(const float* __restrict__ in,
                                 float* __restrict__ out, int rows, int cols)
{
    __shared__ float tile[32][33];
    int bx = blockIdx.x * 32, by = blockIdx.y * 32;
    int x = bx + threadIdx.x;
    #pragma unroll
    for (int j = 0; j < 32; j += 8) {
        int y = by + threadIdx.y + j;
        if (y < rows && x < cols) tile[threadIdx.y + j][threadIdx.x] = in[(size_t)y * cols + x];
    }
    __syncthreads();
    int x2 = by + threadIdx.x;
    #pragma unroll
    for (int j = 0; j < 32; j += 8) {
        int y2 = bx + threadIdx.y + j;
        if (y2 < cols && x2 < rows) out[(size_t)y2 * rows + x2] = tile[threadIdx.x][threadIdx.y + j];
    }
}

// ---------------- tf32 tensor-core GEMM: projections -------------------------
// C[g][co] = sum_c A[c][g] * B[c][co] + bias[co]
__global__ void __launch_bounds__(256) gemm_proj_tc(
    const float* __restrict__ A, const float* __restrict__ B,
    const float* __restrict__ bias, float* __restrict__ Cout, int ldb)
{
    extern __shared__ uint32_t sm[];

    int g0 = blockIdx.x * BM;
    int bn = blockIdx.y;
    int n  = g0 / T_DIM;
    int t0 = g0 % T_DIM;
    const float* Aptr = A + (size_t)n * C_DIM * T_DIM + t0;
    const float* Bptr = B + bn * BN;

    int tid  = threadIdx.x;
    int lane = tid & 31, warp = tid >> 5;
    int wm = warp >> 1, wn = warp & 1;
    int kcL = lane & 3, rG = lane >> 2;

    float acc[2][8][4];
    #pragma unroll
    for (int a = 0; a < 2; a++)
        #pragma unroll
        for (int b = 0; b < 8; b++)
            #pragma unroll
            for (int c = 0; c < 4; c++) acc[a][b][c] = 0.f;

    // prime stage 0
    {
        float ra[16], rb[16];
        ldg_tile(Aptr, T_DIM, 0, tid, ra);
        ldg_tile(Bptr, (size_t)ldb, 0, tid, rb);
        sts_tile(sm, tid, ra);
        sts_tile(sm + STAGE_U32, tid, rb);
    }
    __syncthreads();

    const int NK = C_DIM / BK;
    for (int kt = 0; kt < NK; kt++) {
        int p = kt & 1;
        float ra[16], rb[16];
        if (kt + 1 < NK) {
            ldg_tile(Aptr, T_DIM, kt + 1, tid, ra);
            ldg_tile(Bptr, (size_t)ldb, kt + 1, tid, rb);
        }
        const uint32_t* As = sm + p * BUF_U32;
        const uint32_t* Bs = As + STAGE_U32;
        #pragma unroll
        for (int ks = 0; ks < 4; ks++) {
            const uint32_t* Ab = As + ((ks * 4 + kcL) * APITCH) * 2;
            const uint32_t* Bb = Bs + ((ks * 4 + kcL) * APITCH) * 2;
            uint2 aLo[2], aHi[2];
            #pragma unroll
            for (int mt = 0; mt < 2; mt++) {
                int rm = wm * 32 + mt * 16 + rG;
                aLo[mt] = *(const uint2*)(Ab + rm * 2);
                aHi[mt] = *(const uint2*)(Ab + (rm + 8) * 2);
            }
            #pragma unroll
            for (int nt = 0; nt < 8; nt++) {
                int cn = wn * 64 + nt * 8 + rG;
                uint2 bb = *(const uint2*)(Bb + cn * 2);
                #pragma unroll
                for (int mt = 0; mt < 2; mt++)
                    mma_tf32(acc[mt][nt], aLo[mt].x, aHi[mt].x, aLo[mt].y, aHi[mt].y,
                             bb.x, bb.y);
            }
        }
        if (kt + 1 < NK) {
            uint32_t* d = sm + (p ^ 1) * BUF_U32;
            sts_tile(d, tid, ra);
            sts_tile(d + STAGE_U32, tid, rb);
        }
        __syncthreads();
    }

    // epilogue: [g][512] with bias
    #pragma unroll
    for (int nt = 0; nt < 8; nt++) {
        int n0 = bn * BN + wn * 64 + nt * 8 + 2 * kcL;
        float b0 = bias[n0], b1 = bias[n0 + 1];
        #pragma unroll
        for (int mt = 0; mt < 2; mt++) {
            int r = wm * 32 + mt * 16 + rG;
            float2 lo = make_float2(acc[mt][nt][0] + b0, acc[mt][nt][1] + b1);
            float2 hi = make_float2(acc[mt][nt][2] + b0, acc[mt][nt][3] + b1);
            *(float2*)&Cout[(size_t)(g0 + r) * C_DIM + n0]     = lo;
            *(float2*)&Cout[(size_t)(g0 + r + 8) * C_DIM + n0] = hi;
        }
    }
}

// ---------------- tf32 tensor-core GEMM: out-proj + mask + residual ----------
// out[n][co][t] = (sum_c AOt[c][g] * WtOut[c][co] + b_out[co]) * mask[n][t] + x[n][co][t]
__global__ void __launch_bounds__(256) gemm_out_tc(
    const float* __restrict__ B, const float* __restrict__ bias,
    const float* __restrict__ masks, const float* __restrict__ x,
    float* __restrict__ out)
{
    extern __shared__ uint32_t sm[];

    int g0 = blockIdx.x * BM;
    int bn = blockIdx.y;
    int n  = g0 / T_DIM;
    int t0 = g0 % T_DIM;
    const float* Aptr = g_AOt + g0;
    const float* Bptr = B + bn * BN;

    int tid  = threadIdx.x;
    int lane = tid & 31, warp = tid >> 5;
    int wm = warp >> 1, wn = warp & 1;
    int kcL = lane & 3, rG = lane >> 2;

    float acc[2][8][4];
    #pragma unroll
    for (int a = 0; a < 2; a++)
        #pragma unroll
        for (int b = 0; b < 8; b++)
            #pragma unroll
            for (int c = 0; c < 4; c++) acc[a][b][c] = 0.f;

    {
        float ra[16], rb[16];
        ldg_tile(Aptr, NTOK, 0, tid, ra);
        ldg_tile(Bptr, C_DIM, 0, tid, rb);
        sts_tile(sm, tid, ra);
        sts_tile(sm + STAGE_U32, tid, rb);
    }
    __syncthreads();

    const int NK = C_DIM / BK;
    for (int kt = 0; kt < NK; kt++) {
        int p = kt & 1;
        float ra[16], rb[16];
        if (kt + 1 < NK) {
            ldg_tile(Aptr, NTOK, kt + 1, tid, ra);
            ldg_tile(Bptr, C_DIM, kt + 1, tid, rb);
        }
        const uint32_t* As = sm + p * BUF_U32;
        const uint32_t* Bs = As + STAGE_U32;
        #pragma unroll
        for (int ks = 0; ks < 4; ks++) {
            const uint32_t* Ab = As + ((ks * 4 + kcL) * APITCH) * 2;
            const uint32_t* Bb = Bs + ((ks * 4 + kcL) * APITCH) * 2;
            uint2 aLo[2], aHi[2];
            #pragma unroll
            for (int mt = 0; mt < 2; mt++) {
                int rm = wm * 32 + mt * 16 + rG;
                aLo[mt] = *(const uint2*)(Ab + rm * 2);
                aHi[mt] = *(const uint2*)(Ab + (rm + 8) * 2);
            }
            #pragma unroll
            for (int nt = 0; nt < 8; nt++) {
                int cn = wn * 64 + nt * 8 + rG;
                uint2 bb = *(const uint2*)(Bb + cn * 2);
                #pragma unroll
                for (int mt = 0; mt < 2; mt++)
                    mma_tf32(acc[mt][nt], aLo[mt].x, aHi[mt].x, aLo[mt].y, aHi[mt].y,
                             bb.x, bb.y);
            }
        }
        if (kt + 1 < NK) {
            uint32_t* d = sm + (p ^ 1) * BUF_U32;
            sts_tile(d, tid, ra);
            sts_tile(d + STAGE_U32, tid, rb);
        }
        __syncthreads();
    }

    // epilogue: channel-major with mask & residual (scalar stores)
    #pragma unroll
    for (int mt = 0; mt < 2; mt++) {
        int r = wm * 32 + mt * 16 + rG;
        int tLo = t0 + r;
        float mkLo = masks[(size_t)n * T_DIM + tLo];
        float mkHi = masks[(size_t)n * T_DIM + tLo + 8];
        #pragma unroll
        for (int nt = 0; nt < 8; nt++) {
            int co = bn * BN + wn * 64 + nt * 8 + 2 * kcL;
            #pragma unroll
            for (int cj = 0; cj < 2; cj++) {
                float bb = bias[co + cj];
                size_t iLo = ((size_t)(n * C_DIM + co + cj)) * T_DIM + tLo;
                out[iLo]     = (acc[mt][nt][cj]     + bb) * mkLo + x[iLo];
                out[iLo + 8] = (acc[mt][nt][2 + cj] + bb) * mkHi + x[iLo + 8];
            }
        }
    }
}

// ---------------- attention: one block per (chunk, head) --------------------
__global__ void __launch_bounds__(256) attn_kernel(const float* __restrict__ masks)
{
    __shared__ float bufA[64 * 64];  // Q^T [d][q]   -> then S [q][k]
    __shared__ float bufB[64 * 64];  // K^T [d][k]   -> then P^T [k][q]
    __shared__ float bufC[64 * 64];  // V   [k][d]

    int cb = blockIdx.x;
    int h  = blockIdx.y;
    int g0 = cb * CHUNK_SZ;
    int n  = g0 / T_DIM;
    int t0 = g0 % T_DIM;

    int tid  = threadIdx.x;
    int qrow = tid >> 2;
    int dseg = (tid & 3) * 16;

    const float* qp = g_QP + (size_t)(g0 + qrow) * C_DIM + h * DH + dseg;
    const float* kp = g_KP + (size_t)(g0 + qrow) * C_DIM + h * DH + dseg;
    const float* vp = g_VP + (size_t)(g0 + qrow) * C_DIM + h * DH + dseg;

    #pragma unroll
    for (int i = 0; i < 4; i++) {
        int d = dseg + i * 4;
        float4 tq = *(const float4*)(qp + i * 4);
        bufA[(d+0)*64 + qrow] = tq.x; bufA[(d+1)*64 + qrow] = tq.y;
        bufA[(d+2)*64 + qrow] = tq.z; bufA[(d+3)*64 + qrow] = tq.w;
        float4 tk = *(const float4*)(kp + i * 4);
        bufB[(d+0)*64 + qrow] = tk.x; bufB[(d+1)*64 + qrow] = tk.y;
        bufB[(d+2)*64 + qrow] = tk.z; bufB[(d+3)*64 + qrow] = tk.w;
        float4 tv = *(const float4*)(vp + i * 4);
        *(float4*)(&bufC[qrow * 64 + d]) = tv;
    }
    __syncthreads();

    int ty = tid >> 4, tx = tid & 15;

    float s[4][4];
    #pragma unroll
    for (int i = 0; i < 4; i++)
        #pragma unroll
        for (int j = 0; j < 4; j++) s[i][j] = 0.f;
    #pragma unroll 8
    for (int d = 0; d < 64; d++) {
        float4 a = *(const float4*)(&bufA[d * 64 + ty * 4]);
        float4 b = *(const float4*)(&bufB[d * 64 + tx * 4]);
        float av[4] = {a.x, a.y, a.z, a.w};
        float bv[4] = {b.x, b.y, b.z, b.w};
        #pragma unroll
        for (int i = 0; i < 4; i++)
            #pragma unroll
            for (int j = 0; j < 4; j++) s[i][j] = fmaf(av[i], bv[j], s[i][j]);
    }
    __syncthreads();

    #pragma unroll
    for (int i = 0; i < 4; i++) {
        float4 sv = make_float4(s[i][0], s[i][1], s[i][2], s[i][3]);
        *(float4*)(&bufA[(ty * 4 + i) * 64 + tx * 4]) = sv;
    }
    __syncthreads();

    int warp = tid >> 5, lane = tid & 31;
    const float scale = 0.125f;
    const float* mrow = masks + (size_t)n * T_DIM + t0;
    float mk1 = (mrow[lane]      > 0.f) ? 0.f : NEG_INF;
    float mk2 = (mrow[lane + 32] > 0.f) ? 0.f : NEG_INF;
    for (int r = warp; r < 64; r += 8) {
        float v1 = bufA[r * 64 + lane]      * scale + mk1;
        float v2 = bufA[r * 64 + lane + 32] * scale + mk2;
        float mx = fmaxf(v1, v2);
        #pragma unroll
        for (int o = 16; o; o >>= 1) mx = fmaxf(mx, __shfl_xor_sync(0xffffffffu, mx, o));
        float e1 = __expf(v1 - mx);
        float e2 = __expf(v2 - mx);
        float sm = e1 + e2;
        #pragma unroll
        for (int o = 16; o; o >>= 1) sm += __shfl_xor_sync(0xffffffffu, sm, o);
        float inv = 1.f / sm;
        bufB[lane * 64 + r]        = e1 * inv;
        bufB[(lane + 32) * 64 + r] = e2 * inv;
    }
    __syncthreads();

    float o[4][4];
    #pragma unroll
    for (int i = 0; i < 4; i++)
        #pragma unroll
        for (int j = 0; j < 4; j++) o[i][j] = 0.f;
    #pragma unroll 8
    for (int k = 0; k < 64; k++) {
        float4 a = *(const float4*)(&bufB[k * 64 + ty * 4]);
        float4 b = *(const float4*)(&bufC[k * 64 + tx * 4]);
        float av[4] = {a.x, a.y, a.z, a.w};
        float bv[4] = {b.x, b.y, b.z, b.w};
        #pragma unroll
        for (int i = 0; i < 4; i++)
            #pragma unroll
            for (int j = 0; j < 4; j++) o[i][j] = fmaf(av[i], bv[j], o[i][j]);
    }

    #pragma unroll
    for (int j = 0; j < 4; j++) {
        int co = h * DH + tx * 4 + j;
        float4 ov = make_float4(o[0][j], o[1][j], o[2][j], o[3][j]);
        *(float4*)(&g_AOt[(size_t)co * NTOK + g0 + ty * 4]) = ov;
    }
}

// ---------------- InstanceNorm1d over T per (n,c) row ----------------------
__global__ void __launch_bounds__(256) inorm_kernel(float* __restrict__ out)
{
    __shared__ float red[18];
    int row = blockIdx.x;
    float* p = out + (size_t)row * T_DIM;
    int tid = threadIdx.x;

    float4 v[4];
    float s = 0.f, s2 = 0.f;
    #pragma unroll
    for (int i = 0; i < 4; i++) {
        v[i] = *(const float4*)(p + i * 1024 + tid * 4);
        s  += v[i].x + v[i].y + v[i].z + v[i].w;
        s2 += v[i].x * v[i].x + v[i].y * v[i].y + v[i].z * v[i].z + v[i].w * v[i].w;
    }
    #pragma unroll
    for (int o = 16; o; o >>= 1) {
        s  += __shfl_xor_sync(0xffffffffu, s,  o);
        s2 += __shfl_xor_sync(0xffffffffu, s2, o);
    }
    int warp = tid >> 5, lane = tid & 31;
    if (lane == 0) { red[warp] = s; red[8 + warp] = s2; }
    __syncthreads();
    if (warp == 0) {
        float a  = (lane < 8) ? red[lane]     : 0.f;
        float a2 = (lane < 8) ? red[8 + lane] : 0.f;
        #pragma unroll
        for (int o = 4; o; o >>= 1) {
            a  += __shfl_xor_sync(0xffffffffu, a,  o);
            a2 += __shfl_xor_sync(0xffffffffu, a2, o);
        }
        if (lane == 0) { red[16] = a; red[17] = a2; }
    }
    __syncthreads();
    float mu  = red[16] * (1.f / T_DIM);
    float var = red[17] * (1.f / T_DIM) - mu * mu;
    float rs  = rsqrtf(var + 1e-5f);
    #pragma unroll
    for (int i = 0; i < 4; i++) {
        float4 r;
        r.x = (v[i].x - mu) * rs; r.y = (v[i].y - mu) * rs;
        r.z = (v[i].z - mu) * rs; r.w = (v[i].w - mu) * rs;
        *(float4*)(p + i * 1024 + tid * 4) = r;
    }
}

// ---------------- launch ----------------------------------------------------
extern "C" void kernel_launch(void* const* d_in, const int* in_sizes, int n_in,
                              void* d_out, int out_size)
{
    const float* x     = (const float*)d_in[0];
    const float* q     = (const float*)d_in[1];
    const float* k     = (const float*)d_in[2];
    const float* v     = (const float*)d_in[3];
    const float* masks = (const float*)d_in[4];
    const float* W_in  = (const float*)d_in[5];
    const float* b_in  = (const float*)d_in[6];
    const float* W_out = (const float*)d_in[7];
    const float* b_out = (const float*)d_in[8];
    float* out = (float*)d_out;

    float *WtIn, *WtOut;
    cudaGetSymbolAddress((void**)&WtIn,  g_WtIn);
    cudaGetSymbolAddress((void**)&WtOut, g_WtOut);
    float *QP, *KP, *VP;
    cudaGetSymbolAddress((void**)&QP, g_QP);
    cudaGetSymbolAddress((void**)&KP, g_KP);
    cudaGetSymbolAddress((void**)&VP, g_VP);

    static bool attr_done = false;
    if (!attr_done) {
        cudaFuncSetAttribute(gemm_proj_tc, cudaFuncAttributeMaxDynamicSharedMemorySize,
                             SMEM_U32 * 4);
        cudaFuncSetAttribute(gemm_out_tc, cudaFuncAttributeMaxDynamicSharedMemorySize,
                             SMEM_U32 * 4);
        attr_done = true;
    }

    transpose_kernel<<<dim3(512 / 32, 1536 / 32), dim3(32, 8)>>>(W_in,  WtIn,  1536, 512);
    transpose_kernel<<<dim3(512 / 32,  512 / 32), dim3(32, 8)>>>(W_out, WtOut,  512, 512);

    dim3 gg(NTOK / BM, C_DIM / BN);
    size_t smem = SMEM_U32 * 4;
    gemm_proj_tc<<<gg, 256, smem>>>(q, WtIn + 0,    b_in + 0,    QP, 3 * C_DIM);
    gemm_proj_tc<<<gg, 256, smem>>>(k, WtIn + 512,  b_in + 512,  KP, 3 * C_DIM);
    gemm_proj_tc<<<gg, 256, smem>>>(v, WtIn + 1024, b_in + 1024, VP, 3 * C_DIM);

    attn_kernel<<<dim3(NTOK / CHUNK_SZ, H_HEADS), 256>>>(masks);

    gemm_out_tc<<<gg, 256, smem>>>(WtOut, b_out, masks, x, out);

    inorm_kernel<<<N_BATCH * C_DIM, 256>>>(out);
}

// round 4
// speedup vs baseline: 2.3684x; 1.1238x over previous
#include <cuda_runtime.h>
#include <cuda_bf16.h>
#include <cstdint>

#define N_BATCH 4
#define C_DIM   512
#define T_DIM   4096
#define NTOK    (N_BATCH * T_DIM)   // 16384
#define H_HEADS 8
#define DH      64
#define CHUNK_SZ 64
#define NEG_INF (-1e9f)

// ---------------- GEMM tiling -------------------------------------------------
#define PBM 256
#define PBN 128
#define PBK 32
#define NKT (C_DIM / PBK)      // 16
#define PA_PITCH 260           // uint2 pitch (m=256 + pad), 260 % 16 == 4 (conflict-free frags)
#define PB_PITCH 132           // uint2 pitch (n=128 + pad), 132 % 16 == 4
#define PA_U32 (16 * PA_PITCH * 2)   // 8320
#define PB_U32 (16 * PB_PITCH * 2)   // 4224
#define PSTAGE_U32 (PA_U32 + PB_U32) // 12544
#define PSMEM_BYTES (2 * PSTAGE_U32 * 4)  // 100352

// ---------------- attention tiling -------------------------------------------
#define AP 68                  // uint2 pitch, 68 % 16 == 4
#define ABUF (32 * AP * 2)     // 4352 u32 per buffer
#define ASMEM_BYTES ((4 * ABUF + 64) * 4)  // 4 buffers + mask addends = 69888

// ---------------- scratch (device globals; no allocation allowed) -------------
__device__ float g_WtIn[C_DIM * 3 * C_DIM];   // [c][co3]
__device__ float g_WtOut[C_DIM * C_DIM];      // [c][co]
__device__ float g_QP[(size_t)NTOK * C_DIM];  // [g][co]
__device__ float g_KP[(size_t)NTOK * C_DIM];
__device__ float g_VP[(size_t)NTOK * C_DIM];
__device__ float g_AO[(size_t)NTOK * C_DIM];  // attn out [g][co]

// ---------------- helpers -----------------------------------------------------
__device__ __forceinline__ uint32_t f2tf32(float x) {
    uint32_t u;
    asm("cvt.rna.tf32.f32 %0, %1;" : "=r"(u) : "f"(x));
    return u;
}

__device__ __forceinline__ void mma_tf32(float* c,
                                         uint32_t a0, uint32_t a1, uint32_t a2, uint32_t a3,
                                         uint32_t b0, uint32_t b1) {
    asm volatile(
        "mma.sync.aligned.m16n8k8.row.col.f32.tf32.tf32.f32 "
        "{%0,%1,%2,%3}, {%4,%5,%6,%7}, {%8,%9}, {%0,%1,%2,%3};\n"
        : "+f"(c[0]), "+f"(c[1]), "+f"(c[2]), "+f"(c[3])
        : "r"(a0), "r"(a1), "r"(a2), "r"(a3), "r"(b0), "r"(b1));
}

// ---------------- transpose: in[rows][cols] -> out[cols][rows] -----------------
__global__ void transpose_kernel(const float* __restrict__ in,
                                 float* __restrict__ out, int rows, int cols)
{
    __shared__ float tile[32][33];
    int bx = blockIdx.x * 32, by = blockIdx.y * 32;
    int x = bx + threadIdx.x;
    #pragma unroll
    for (int j = 0; j < 32; j += 8) {
        int y = by + threadIdx.y + j;
        if (y < rows && x < cols) tile[threadIdx.y + j][threadIdx.x] = in[(size_t)y * cols + x];
    }
    __syncthreads();
    int x2 = by + threadIdx.x;
    #pragma unroll
    for (int j = 0; j < 32; j += 8) {
        int y2 = bx + threadIdx.y + j;
        if (y2 < cols && x2 < rows) out[(size_t)y2 * rows + x2] = tile[threadIdx.x][threadIdx.y + j];
    }
}

// ======================= GEMM building blocks =================================
// smem stage layout: 16 slots (ks*4+kc) of uint2 rows; element (kloc, m):
//   slot = (kloc>>3)*4 + (kloc&3), kh = (kloc>>2)&1
//   u32 addr = (slot*PITCH + m)*2 + kh   -> pair (k, k+4) contiguous (uint2)

// A loader for strided-k source (proj inputs [c][t]: k row-stride = ld, m contiguous)
struct LdrStrided {
    float r[4][8];
    __device__ __forceinline__ void ldg(const float* base, size_t ld, int kt, int tid) {
        int kp0 = (tid >> 6) * 4;
        int m0  = (tid & 63) * 4;
        #pragma unroll
        for (int i = 0; i < 4; i++) {
            int kp = kp0 + i;
            int kloc = (kp >> 2) * 8 + (kp & 3);
            const float* p = base + (size_t)(kt * PBK + kloc) * ld + m0;
            *(float4*)&r[i][0] = *(const float4*)p;
            *(float4*)&r[i][4] = *(const float4*)(p + 4 * ld);
        }
    }
    __device__ __forceinline__ void sts(uint32_t* buf, int tid) {
        int kp0 = (tid >> 6) * 4;
        int m0  = (tid & 63) * 4;
        #pragma unroll
        for (int i = 0; i < 4; i++) {
            int kp = kp0 + i;
            uint32_t* d = buf + ((uint32_t)kp * PA_PITCH + m0) * 2;
            uint4 u0 = make_uint4(f2tf32(r[i][0]), f2tf32(r[i][4]),
                                  f2tf32(r[i][1]), f2tf32(r[i][5]));
            uint4 u1 = make_uint4(f2tf32(r[i][2]), f2tf32(r[i][6]),
                                  f2tf32(r[i][3]), f2tf32(r[i][7]));
            *(uint4*)d = u0;
            *(uint4*)(d + 4) = u1;
        }
    }
};

// A loader for k-contiguous source (AO [g][co]: k contiguous, m row-stride = ld)
struct LdrKMajorA {
    float r[4][8];
    __device__ __forceinline__ void ldg(const float* base, size_t ld, int kt, int tid) {
        int koct = tid & 3;
        int mb   = tid >> 2;
        #pragma unroll
        for (int i = 0; i < 4; i++) {
            int m = mb + 64 * i;
            const float* p = base + (size_t)m * ld + kt * PBK + koct * 8;
            *(float4*)&r[i][0] = *(const float4*)p;
            *(float4*)&r[i][4] = *(const float4*)(p + 4);
        }
    }
    __device__ __forceinline__ void sts(uint32_t* buf, int tid) {
        int koct = tid & 3;
        int mb   = tid >> 2;
        #pragma unroll
        for (int i = 0; i < 4; i++) {
            int m = mb + 64 * i;
            #pragma unroll
            for (int e = 0; e < 4; e++) {
                uint32_t* d = buf + ((uint32_t)(koct * 4 + e) * PA_PITCH + m) * 2;
                *(uint2*)d = make_uint2(f2tf32(r[i][e]), f2tf32(r[i][4 + e]));
            }
        }
    }
};

// B loader (Wt [c][co]: k row-stride = ld, n contiguous)
struct LdrB {
    float r[2][8];
    __device__ __forceinline__ void ldg(const float* base, size_t ld, int kt, int tid) {
        int kp0 = (tid >> 5) * 2;
        int n0  = (tid & 31) * 4;
        #pragma unroll
        for (int i = 0; i < 2; i++) {
            int kp = kp0 + i;
            int kloc = (kp >> 2) * 8 + (kp & 3);
            const float* p = base + (size_t)(kt * PBK + kloc) * ld + n0;
            *(float4*)&r[i][0] = *(const float4*)p;
            *(float4*)&r[i][4] = *(const float4*)(p + 4 * ld);
        }
    }
    __device__ __forceinline__ void sts(uint32_t* buf, int tid) {
        int kp0 = (tid >> 5) * 2;
        int n0  = (tid & 31) * 4;
        #pragma unroll
        for (int i = 0; i < 2; i++) {
            int kp = kp0 + i;
            uint32_t* d = buf + ((uint32_t)kp * PB_PITCH + n0) * 2;
            uint4 u0 = make_uint4(f2tf32(r[i][0]), f2tf32(r[i][4]),
                                  f2tf32(r[i][1]), f2tf32(r[i][5]));
            uint4 u1 = make_uint4(f2tf32(r[i][2]), f2tf32(r[i][6]),
                                  f2tf32(r[i][3]), f2tf32(r[i][7]));
            *(uint4*)d = u0;
            *(uint4*)(d + 4) = u1;
        }
    }
};

// MMA mainloop over one smem stage (ks = 0..3), warp tile 64x64
__device__ __forceinline__ void mma_stage(const uint32_t* As, const uint32_t* Bs,
                                          float acc[4][8][4], int wm, int wn,
                                          int q, int rG) {
    #pragma unroll
    for (int ks = 0; ks < 4; ks++) {
        const uint32_t* Ab = As + ((uint32_t)(ks * 4 + q) * PA_PITCH) * 2;
        const uint32_t* Bb = Bs + ((uint32_t)(ks * 4 + q) * PB_PITCH) * 2;
        uint2 aL[4], aH[4];
        #pragma unroll
        for (int mt = 0; mt < 4; mt++) {
            int rm = wm * 64 + mt * 16 + rG;
            aL[mt] = *(const uint2*)(Ab + rm * 2);
            aH[mt] = *(const uint2*)(Ab + (rm + 8) * 2);
        }
        #pragma unroll
        for (int nt = 0; nt < 8; nt++) {
            uint2 bb = *(const uint2*)(Bb + (wn * 64 + nt * 8 + rG) * 2);
            #pragma unroll
            for (int mt = 0; mt < 4; mt++)
                mma_tf32(acc[mt][nt], aL[mt].x, aH[mt].x, aL[mt].y, aH[mt].y, bb.x, bb.y);
        }
    }
}

// ---------------- GEMM: projections ------------------------------------------
// Cout[g][co(512)] = sum_c A[n][c][t] * Wt[c][co] + bias[co]
__global__ void __launch_bounds__(256) gemm_proj_mma(
    const float* __restrict__ A, const float* __restrict__ B,
    const float* __restrict__ bias, float* __restrict__ Cout, int ldb)
{
    extern __shared__ uint32_t sm[];
    int g0 = blockIdx.x * PBM, bn = blockIdx.y;
    int n = g0 / T_DIM, t0 = g0 % T_DIM;
    const float* Aptr = A + (size_t)n * C_DIM * T_DIM + t0;
    const float* Bptr = B + bn * PBN;

    int tid = threadIdx.x, lane = tid & 31, wid = tid >> 5;
    int wm = wid >> 1, wn = wid & 1, q = lane & 3, rG = lane >> 2;

    float acc[4][8][4];
    #pragma unroll
    for (int a = 0; a < 4; a++)
        #pragma unroll
        for (int b = 0; b < 8; b++)
            #pragma unroll
            for (int c = 0; c < 4; c++) acc[a][b][c] = 0.f;

    LdrStrided la;
    LdrB lb;
    la.ldg(Aptr, T_DIM, 0, tid);
    lb.ldg(Bptr, ldb, 0, tid);
    la.sts(sm, tid);
    lb.sts(sm + PA_U32, tid);
    __syncthreads();

    for (int kt = 0; kt < NKT; kt++) {
        int p = kt & 1;
        if (kt + 1 < NKT) {
            la.ldg(Aptr, T_DIM, kt + 1, tid);
            lb.ldg(Bptr, ldb, kt + 1, tid);
        }
        const uint32_t* As = sm + p * PSTAGE_U32;
        mma_stage(As, As + PA_U32, acc, wm, wn, q, rG);
        if (kt + 1 < NKT) {
            uint32_t* d = sm + (p ^ 1) * PSTAGE_U32;
            la.sts(d, tid);
            lb.sts(d + PA_U32, tid);
        }
        __syncthreads();
    }

    #pragma unroll
    for (int nt = 0; nt < 8; nt++) {
        int cb = bn * PBN + wn * 64 + nt * 8 + 2 * q;
        float b0 = bias[cb], b1 = bias[cb + 1];
        #pragma unroll
        for (int mt = 0; mt < 4; mt++) {
            int r = g0 + wm * 64 + mt * 16 + rG;
            *(float2*)&Cout[(size_t)r * C_DIM + cb] =
                make_float2(acc[mt][nt][0] + b0, acc[mt][nt][1] + b1);
            *(float2*)&Cout[(size_t)(r + 8) * C_DIM + cb] =
                make_float2(acc[mt][nt][2] + b0, acc[mt][nt][3] + b1);
        }
    }
}

// ---------------- GEMM: out-proj + bias + mask + residual ---------------------
// out[n][co][t] = (sum_c AO[g][c] * WtOut[c][co] + b[co]) * mask[n][t] + x[n][co][t]
__global__ void __launch_bounds__(256) gemm_out_mma(
    const float* __restrict__ B, const float* __restrict__ bias,
    const float* __restrict__ masks, const float* __restrict__ x,
    float* __restrict__ out)
{
    extern __shared__ uint32_t sm[];
    int g0 = blockIdx.x * PBM, bn = blockIdx.y;
    int n = g0 / T_DIM, t0 = g0 % T_DIM;
    const float* Aptr = g_AO + (size_t)g0 * C_DIM;
    const float* Bptr = B + bn * PBN;

    int tid = threadIdx.x, lane = tid & 31, wid = tid >> 5;
    int wm = wid >> 1, wn = wid & 1, q = lane & 3, rG = lane >> 2;

    float acc[4][8][4];
    #pragma unroll
    for (int a = 0; a < 4; a++)
        #pragma unroll
        for (int b = 0; b < 8; b++)
            #pragma unroll
            for (int c = 0; c < 4; c++) acc[a][b][c] = 0.f;

    LdrKMajorA la;
    LdrB lb;
    la.ldg(Aptr, C_DIM, 0, tid);
    lb.ldg(Bptr, C_DIM, 0, tid);
    la.sts(sm, tid);
    lb.sts(sm + PA_U32, tid);
    __syncthreads();

    for (int kt = 0; kt < NKT; kt++) {
        int p = kt & 1;
        if (kt + 1 < NKT) {
            la.ldg(Aptr, C_DIM, kt + 1, tid);
            lb.ldg(Bptr, C_DIM, kt + 1, tid);
        }
        const uint32_t* As = sm + p * PSTAGE_U32;
        mma_stage(As, As + PA_U32, acc, wm, wn, q, rG);
        if (kt + 1 < NKT) {
            uint32_t* d = sm + (p ^ 1) * PSTAGE_U32;
            la.sts(d, tid);
            lb.sts(d + PA_U32, tid);
        }
        __syncthreads();
    }

    // epilogue: channel-major + mask + residual
    #pragma unroll
    for (int mt = 0; mt < 4; mt++) {
        int r = wm * 64 + mt * 16 + rG;
        int tA = t0 + r;
        float mkA = masks[(size_t)n * T_DIM + tA];
        float mkB = masks[(size_t)n * T_DIM + tA + 8];
        #pragma unroll
        for (int nt = 0; nt < 8; nt++) {
            int co = bn * PBN + wn * 64 + nt * 8 + 2 * q;
            #pragma unroll
            for (int cj = 0; cj < 2; cj++) {
                float bb = bias[co + cj];
                size_t iA = ((size_t)(n * C_DIM + co + cj)) * T_DIM + tA;
                out[iA]     = (acc[mt][nt][cj]     + bb) * mkA + x[iA];
                out[iA + 8] = (acc[mt][nt][2 + cj] + bb) * mkB + x[iA + 8];
            }
        }
    }
}

// ---------------- attention via mma.sync: block per (chunk, head) -------------
__global__ void __launch_bounds__(128) attn_mma(const float* __restrict__ masks)
{
    extern __shared__ uint32_t ash[];
    uint32_t* sQ = ash;
    uint32_t* sK = ash + ABUF;
    uint32_t* sV = ash + 2 * ABUF;
    uint32_t* sP = ash + 3 * ABUF;
    float* skm   = (float*)(ash + 4 * ABUF);

    int cb = blockIdx.x, h = blockIdx.y;
    int g0 = cb * CHUNK_SZ;
    int n = g0 / T_DIM, t0 = g0 % T_DIM;
    int tid = threadIdx.x, lane = tid & 31, w = tid >> 5;
    int q = lane & 3, rG = lane >> 2;

    if (tid < 64)
        skm[tid] = (masks[(size_t)n * T_DIM + t0 + tid] > 0.f) ? 0.f : NEG_INF;

    // ---- load Q, K: rows = token m, slots along d; pairs (d, d+4) ----
    {
        int m = tid >> 1, dh = (tid & 1) * 32;
        const float* qp = g_QP + (size_t)(g0 + m) * C_DIM + h * DH;
        const float* kp = g_KP + (size_t)(g0 + m) * C_DIM + h * DH;
        #pragma unroll
        for (int i = 0; i < 4; i++) {
            int d0 = dh + i * 8;
            int slot0 = d0 >> 1;    // (d0>>3)*4, d0 multiple of 8
            float4 v1 = *(const float4*)(qp + d0);
            float4 v2 = *(const float4*)(qp + d0 + 4);
            uint32_t* dst = sQ + ((uint32_t)slot0 * AP + m) * 2;
            *(uint2*)(dst)          = make_uint2(f2tf32(v1.x), f2tf32(v2.x));
            *(uint2*)(dst + AP * 2) = make_uint2(f2tf32(v1.y), f2tf32(v2.y));
            *(uint2*)(dst + AP * 4) = make_uint2(f2tf32(v1.z), f2tf32(v2.z));
            *(uint2*)(dst + AP * 6) = make_uint2(f2tf32(v1.w), f2tf32(v2.w));
            v1 = *(const float4*)(kp + d0);
            v2 = *(const float4*)(kp + d0 + 4);
            dst = sK + ((uint32_t)slot0 * AP + m) * 2;
            *(uint2*)(dst)          = make_uint2(f2tf32(v1.x), f2tf32(v2.x));
            *(uint2*)(dst + AP * 2) = make_uint2(f2tf32(v1.y), f2tf32(v2.y));
            *(uint2*)(dst + AP * 4) = make_uint2(f2tf32(v1.z), f2tf32(v2.z));
            *(uint2*)(dst + AP * 6) = make_uint2(f2tf32(v1.w), f2tf32(v2.w));
        }
    }
    // ---- load V^T: rows = d, slots along token; pairs (t, t+4) ----
    {
        int tp = tid >> 2;                       // slot 0..31
        int t  = (tp >> 2) * 8 + (tp & 3);       // kloc
        const float* vp  = g_VP + (size_t)(g0 + t) * C_DIM + h * DH;
        const float* vp4 = vp + 4 * C_DIM;
        #pragma unroll
        for (int i = 0; i < 4; i++) {
            int d0 = ((tid & 3) * 4 + i) * 4;
            float4 v1 = *(const float4*)(vp + d0);
            float4 v2 = *(const float4*)(vp4 + d0);
            uint32_t* dst = sV + ((uint32_t)tp * AP + d0) * 2;
            *(uint4*)dst = make_uint4(f2tf32(v1.x), f2tf32(v2.x), f2tf32(v1.y), f2tf32(v2.y));
            *(uint4*)(dst + 4) = make_uint4(f2tf32(v1.z), f2tf32(v2.z), f2tf32(v1.w), f2tf32(v2.w));
        }
    }
    __syncthreads();

    int mA = w * 16 + rG;

    // ---- S = Q K^T (warp rows mA, mA+8) ----
    float s[8][4];
    #pragma unroll
    for (int nt = 0; nt < 8; nt++)
        #pragma unroll
        for (int j = 0; j < 4; j++) s[nt][j] = 0.f;
    #pragma unroll
    for (int ks = 0; ks < 8; ks++) {
        const uint32_t* Ab = sQ + ((uint32_t)(ks * 4 + q) * AP) * 2;
        const uint32_t* Bb = sK + ((uint32_t)(ks * 4 + q) * AP) * 2;
        uint2 aL = *(const uint2*)(Ab + mA * 2);
        uint2 aH = *(const uint2*)(Ab + (mA + 8) * 2);
        #pragma unroll
        for (int nt = 0; nt < 8; nt++) {
            uint2 bb = *(const uint2*)(Bb + (nt * 8 + rG) * 2);
            mma_tf32(s[nt], aL.x, aH.x, aL.y, aH.y, bb.x, bb.y);
        }
    }

    // ---- softmax in registers (rows mA and mA+8) ----
    const float scale = 0.125f;
    float mxA = -3.4e38f, mxB = -3.4e38f;
    #pragma unroll
    for (int nt = 0; nt < 8; nt++) {
        int c0 = nt * 8 + 2 * q;
        float a0 = skm[c0], a1 = skm[c0 + 1];
        s[nt][0] = s[nt][0] * scale + a0;
        s[nt][1] = s[nt][1] * scale + a1;
        s[nt][2] = s[nt][2] * scale + a0;
        s[nt][3] = s[nt][3] * scale + a1;
        mxA = fmaxf(mxA, fmaxf(s[nt][0], s[nt][1]));
        mxB = fmaxf(mxB, fmaxf(s[nt][2], s[nt][3]));
    }
    mxA = fmaxf(mxA, __shfl_xor_sync(0xffffffffu, mxA, 1));
    mxA = fmaxf(mxA, __shfl_xor_sync(0xffffffffu, mxA, 2));
    mxB = fmaxf(mxB, __shfl_xor_sync(0xffffffffu, mxB, 1));
    mxB = fmaxf(mxB, __shfl_xor_sync(0xffffffffu, mxB, 2));
    float sA = 0.f, sB = 0.f;
    #pragma unroll
    for (int nt = 0; nt < 8; nt++) {
        s[nt][0] = __expf(s[nt][0] - mxA);
        s[nt][1] = __expf(s[nt][1] - mxA);
        s[nt][2] = __expf(s[nt][2] - mxB);
        s[nt][3] = __expf(s[nt][3] - mxB);
        sA += s[nt][0] + s[nt][1];
        sB += s[nt][2] + s[nt][3];
    }
    sA += __shfl_xor_sync(0xffffffffu, sA, 1);
    sA += __shfl_xor_sync(0xffffffffu, sA, 2);
    sB += __shfl_xor_sync(0xffffffffu, sB, 1);
    sB += __shfl_xor_sync(0xffffffffu, sB, 2);
    float iA = 1.f / sA, iB = 1.f / sB;

    // ---- write P into sP (A-operand layout: rows=query, slots along key) ----
    #pragma unroll
    for (int nt = 0; nt < 8; nt++) {
        #pragma unroll
        for (int j = 0; j < 4; j++) {
            int kb = 2 * q + (j & 1);            // key within nt octet
            int slot = nt * 4 + (kb & 3);
            int kh = kb >> 2;
            int m = (j < 2) ? mA : (mA + 8);
            float val = s[nt][j] * ((j < 2) ? iA : iB);
            sP[((uint32_t)slot * AP + m) * 2 + kh] = f2tf32(val);
        }
    }
    __syncwarp();

    // ---- O = P V ----
    float o[8][4];
    #pragma unroll
    for (int nt = 0; nt < 8; nt++)
        #pragma unroll
        for (int j = 0; j < 4; j++) o[nt][j] = 0.f;
    #pragma unroll
    for (int ks = 0; ks < 8; ks++) {
        const uint32_t* Ab = sP + ((uint32_t)(ks * 4 + q) * AP) * 2;
        const uint32_t* Bb = sV + ((uint32_t)(ks * 4 + q) * AP) * 2;
        uint2 aL = *(const uint2*)(Ab + mA * 2);
        uint2 aH = *(const uint2*)(Ab + (mA + 8) * 2);
        #pragma unroll
        for (int nt = 0; nt < 8; nt++) {
            uint2 bb = *(const uint2*)(Bb + (nt * 8 + rG) * 2);
            mma_tf32(o[nt], aL.x, aH.x, aL.y, aH.y, bb.x, bb.y);
        }
    }

    // ---- store O to g_AO[g][co] ----
    float* aoA = g_AO + (size_t)(g0 + mA) * C_DIM + h * DH;
    float* aoB = g_AO + (size_t)(g0 + mA + 8) * C_DIM + h * DH;
    #pragma unroll
    for (int nt = 0; nt < 8; nt++) {
        int c0 = nt * 8 + 2 * q;
        *(float2*)(aoA + c0) = make_float2(o[nt][0], o[nt][1]);
        *(float2*)(aoB + c0) = make_float2(o[nt][2], o[nt][3]);
    }
}

// ---------------- InstanceNorm1d over T per (n,c) row -------------------------
__global__ void __launch_bounds__(256) inorm_kernel(float* __restrict__ out)
{
    __shared__ float red[18];
    int row = blockIdx.x;
    float* p = out + (size_t)row * T_DIM;
    int tid = threadIdx.x;

    float4 v[4];
    float s = 0.f, s2 = 0.f;
    #pragma unroll
    for (int i = 0; i < 4; i++) {
        v[i] = *(const float4*)(p + i * 1024 + tid * 4);
        s  += v[i].x + v[i].y + v[i].z + v[i].w;
        s2 += v[i].x * v[i].x + v[i].y * v[i].y + v[i].z * v[i].z + v[i].w * v[i].w;
    }
    #pragma unroll
    for (int o = 16; o; o >>= 1) {
        s  += __shfl_xor_sync(0xffffffffu, s,  o);
        s2 += __shfl_xor_sync(0xffffffffu, s2, o);
    }
    int warp = tid >> 5, lane = tid & 31;
    if (lane == 0) { red[warp] = s; red[8 + warp] = s2; }
    __syncthreads();
    if (warp == 0) {
        float a  = (lane < 8) ? red[lane]     : 0.f;
        float a2 = (lane < 8) ? red[8 + lane] : 0.f;
        #pragma unroll
        for (int o = 4; o; o >>= 1) {
            a  += __shfl_xor_sync(0xffffffffu, a,  o);
            a2 += __shfl_xor_sync(0xffffffffu, a2, o);
        }
        if (lane == 0) { red[16] = a; red[17] = a2; }
    }
    __syncthreads();
    float mu  = red[16] * (1.f / T_DIM);
    float var = red[17] * (1.f / T_DIM) - mu * mu;
    float rs  = rsqrtf(var + 1e-5f);
    #pragma unroll
    for (int i = 0; i < 4; i++) {
        float4 r;
        r.x = (v[i].x - mu) * rs; r.y = (v[i].y - mu) * rs;
        r.z = (v[i].z - mu) * rs; r.w = (v[i].w - mu) * rs;
        *(float4*)(p + i * 1024 + tid * 4) = r;
    }
}

// ---------------- launch -------------------------------------------------------
extern "C" void kernel_launch(void* const* d_in, const int* in_sizes, int n_in,
                              void* d_out, int out_size)
{
    const float* x     = (const float*)d_in[0];
    const float* q     = (const float*)d_in[1];
    const float* k     = (const float*)d_in[2];
    const float* v     = (const float*)d_in[3];
    const float* masks = (const float*)d_in[4];
    const float* W_in  = (const float*)d_in[5];
    const float* b_in  = (const float*)d_in[6];
    const float* W_out = (const float*)d_in[7];
    const float* b_out = (const float*)d_in[8];
    float* out = (float*)d_out;

    float *WtIn, *WtOut, *QP, *KP, *VP;
    cudaGetSymbolAddress((void**)&WtIn,  g_WtIn);
    cudaGetSymbolAddress((void**)&WtOut, g_WtOut);
    cudaGetSymbolAddress((void**)&QP, g_QP);
    cudaGetSymbolAddress((void**)&KP, g_KP);
    cudaGetSymbolAddress((void**)&VP, g_VP);

    static bool attr_done = false;
    if (!attr_done) {
        cudaFuncSetAttribute(gemm_proj_mma, cudaFuncAttributeMaxDynamicSharedMemorySize,
                             PSMEM_BYTES);
        cudaFuncSetAttribute(gemm_out_mma, cudaFuncAttributeMaxDynamicSharedMemorySize,
                             PSMEM_BYTES);
        cudaFuncSetAttribute(attn_mma, cudaFuncAttributeMaxDynamicSharedMemorySize,
                             ASMEM_BYTES);
        attr_done = true;
    }

    transpose_kernel<<<dim3(512 / 32, 1536 / 32), dim3(32, 8)>>>(W_in,  WtIn,  1536, 512);
    transpose_kernel<<<dim3(512 / 32,  512 / 32), dim3(32, 8)>>>(W_out, WtOut,  512, 512);

    dim3 gg(NTOK / PBM, C_DIM / PBN);   // (64, 4)
    gemm_proj_mma<<<gg, 256, PSMEM_BYTES>>>(q, WtIn + 0,    b_in + 0,    QP, 3 * C_DIM);
    gemm_proj_mma<<<gg, 256, PSMEM_BYTES>>>(k, WtIn + 512,  b_in + 512,  KP, 3 * C_DIM);
    gemm_proj_mma<<<gg, 256, PSMEM_BYTES>>>(v, WtIn + 1024, b_in + 1024, VP, 3 * C_DIM);

    attn_mma<<<dim3(NTOK / CHUNK_SZ, H_HEADS), 128, ASMEM_BYTES>>>(masks);

    gemm_out_mma<<<gg, 256, PSMEM_BYTES>>>(WtOut, b_out, masks, x, out);

    inorm_kernel<<<N_BATCH * C_DIM, 256>>>(out);
}

// round 5
// speedup vs baseline: 3.4164x; 1.4425x over previous
#include <cuda_runtime.h>
#include <cuda_bf16.h>
#include <cstdint>

#define N_BATCH 4
#define C_DIM   512
#define T_DIM   4096
#define NTOK    (N_BATCH * T_DIM)   // 16384
#define H_HEADS 8
#define DH      64
#define CHUNK_SZ 64
#define NEG_INF (-1e9f)

// ---------------- fp16 GEMM tiling -------------------------------------------
// CTA tile 128x128, BK=32 (16 f16x2 words -> 8 slots of (kw, kw+4) pairs)
#define PBM 128
#define PBN 128
#define NKT (C_DIM / 32)       // 16
#define GP  132                // uint2 pitch (128 + pad4); 132 % 16 == 4 -> frag LDS conflict-free
#define OPER_U32 (8 * GP * 2)  // one operand stage in u32: 2112
#define STAGE_U32 (2 * OPER_U32)   // A+B: 4224
// total static smem: 2 stages * 4224 u32 = 33792 B

// ---------------- attention tiling -------------------------------------------
#define AP 68
#define ABUF (32 * AP * 2)
#define ASMEM_BYTES ((4 * ABUF + 64) * 4)

// ---------------- scratch ------------------------------------------------------
__device__ float g_QP[(size_t)NTOK * C_DIM];
__device__ float g_KP[(size_t)NTOK * C_DIM];
__device__ float g_VP[(size_t)NTOK * C_DIM];
__device__ float g_AO[(size_t)NTOK * C_DIM];

// ---------------- helpers ------------------------------------------------------
__device__ __forceinline__ uint32_t pack_f16x2(float lo, float hi) {
    uint32_t r;
    asm("cvt.rn.f16x2.f32 %0, %1, %2;" : "=r"(r) : "f"(hi), "f"(lo));
    return r;
}

__device__ __forceinline__ uint32_t f2tf32(float x) {
    uint32_t u;
    asm("cvt.rna.tf32.f32 %0, %1;" : "=r"(u) : "f"(x));
    return u;
}

__device__ __forceinline__ void mma_f16(float* c,
                                        uint32_t a0, uint32_t a1, uint32_t a2, uint32_t a3,
                                        uint32_t b0, uint32_t b1) {
    asm volatile(
        "mma.sync.aligned.m16n8k16.row.col.f32.f16.f16.f32 "
        "{%0,%1,%2,%3}, {%4,%5,%6,%7}, {%8,%9}, {%0,%1,%2,%3};\n"
        : "+f"(c[0]), "+f"(c[1]), "+f"(c[2]), "+f"(c[3])
        : "r"(a0), "r"(a1), "r"(a2), "r"(a3), "r"(b0), "r"(b1));
}

__device__ __forceinline__ void mma_tf32(float* c,
                                         uint32_t a0, uint32_t a1, uint32_t a2, uint32_t a3,
                                         uint32_t b0, uint32_t b1) {
    asm volatile(
        "mma.sync.aligned.m16n8k8.row.col.f32.tf32.tf32.f32 "
        "{%0,%1,%2,%3}, {%4,%5,%6,%7}, {%8,%9}, {%0,%1,%2,%3};\n"
        : "+f"(c[0]), "+f"(c[1]), "+f"(c[2]), "+f"(c[3])
        : "r"(a0), "r"(a1), "r"(a2), "r"(a3), "r"(b0), "r"(b1));
}

// ======================= fp16 GEMM building blocks =============================
// smem word layout per 32-k tile: word(m, kw) = f16x2(src[2kw], src[2kw+1]), kw 0..15
//   slot s = (kw>>3)*4 + (kw&3)  (8 slots), kh = (kw>>2)&1
//   uint2[s*GP + m] = (word(kh=0), word(kh=1))
// fragment read (k16-step ks, quad q): uint2 at ((ks*4+q)*GP + m) = (a0|b0, a2|b1)

// A loader, k-strided source (inputs [c][t]: k = row, m contiguous)
struct LdrAS {
    float4 lo[2][2], hi[2][2];   // [slot-idx][kh]
    __device__ __forceinline__ void ldg(const float* base, int kt, int tid) {
        int w = tid >> 5, m0 = (tid & 31) * 4;
        #pragma unroll
        for (int si = 0; si < 2; si++) {
            int s = 2 * w + si;
            #pragma unroll
            for (int kh = 0; kh < 2; kh++) {
                int kw = (s >> 2) * 8 + kh * 4 + (s & 3);
                const float* p = base + (size_t)(kt * 32 + 2 * kw) * T_DIM + m0;
                lo[si][kh] = *(const float4*)p;
                hi[si][kh] = *(const float4*)(p + T_DIM);
            }
        }
    }
    __device__ __forceinline__ void sts(uint32_t* buf, int tid) {
        int w = tid >> 5, m0 = (tid & 31) * 4;
        #pragma unroll
        for (int si = 0; si < 2; si++) {
            int s = 2 * w + si;
            uint32_t wd[2][4];
            #pragma unroll
            for (int kh = 0; kh < 2; kh++) {
                const float* l = (const float*)&lo[si][kh];
                const float* h = (const float*)&hi[si][kh];
                #pragma unroll
                for (int j = 0; j < 4; j++) wd[kh][j] = pack_f16x2(l[j], h[j]);
            }
            uint32_t* d = buf + ((uint32_t)s * GP + m0) * 2;
            *(uint4*)d       = make_uint4(wd[0][0], wd[1][0], wd[0][1], wd[1][1]);
            *(uint4*)(d + 4) = make_uint4(wd[0][2], wd[1][2], wd[0][3], wd[1][3]);
        }
    }
};

// k-contiguous loader (W [n][k] or AO [m][k])
struct LdrKM {
    float4 v[4][2];
    __device__ __forceinline__ void ldg(const float* base, int ld, int kt, int tid) {
        int mb = tid >> 2, kq = tid & 3;
        #pragma unroll
        for (int i = 0; i < 4; i++) {
            const float* p = base + (size_t)(mb + 32 * i) * ld + kt * 32 + kq * 8;
            v[i][0] = *(const float4*)p;
            v[i][1] = *(const float4*)(p + 4);
        }
    }
    __device__ __forceinline__ void sts(uint32_t* buf, int tid) {
        int mb = tid >> 2, kq = tid & 3;
        int sb = (kq >> 1) * 4, kh = kq & 1;
        #pragma unroll
        for (int i = 0; i < 4; i++) {
            int n = mb + 32 * i;
            const float* f = (const float*)&v[i][0];
            #pragma unroll
            for (int j = 0; j < 4; j++)
                buf[((uint32_t)(sb + j) * GP + n) * 2 + kh] = pack_f16x2(f[2 * j], f[2 * j + 1]);
        }
    }
};

__device__ __forceinline__ void mma_stage16(const uint32_t* As, const uint32_t* Bs,
                                            float acc[4][8][4], int wm, int wn,
                                            int q, int rG) {
    #pragma unroll
    for (int ks = 0; ks < 2; ks++) {
        const uint32_t* Ab = As + ((uint32_t)(ks * 4 + q) * GP) * 2;
        const uint32_t* Bb = Bs + ((uint32_t)(ks * 4 + q) * GP) * 2;
        uint2 aL[4], aH[4];
        #pragma unroll
        for (int mt = 0; mt < 4; mt++) {
            int m = wm * 64 + mt * 16 + rG;
            aL[mt] = *(const uint2*)(Ab + m * 2);
            aH[mt] = *(const uint2*)(Ab + (m + 8) * 2);
        }
        #pragma unroll
        for (int nt = 0; nt < 8; nt++) {
            uint2 bb = *(const uint2*)(Bb + (wn * 64 + nt * 8 + rG) * 2);
            #pragma unroll
            for (int mt = 0; mt < 4; mt++)
                mma_f16(acc[mt][nt], aL[mt].x, aH[mt].x, aL[mt].y, aH[mt].y, bb.x, bb.y);
        }
    }
}

// ---------------- GEMM: projections (fp16 MMA) --------------------------------
// Cout[g][co] = sum_c A[n][c][t] * W[co][c] + bias[co];  W native [co][c]
__global__ void __launch_bounds__(128, 2) gemm_proj_f16(
    const float* __restrict__ A, const float* __restrict__ W,
    const float* __restrict__ bias, float* __restrict__ Cout)
{
    __shared__ uint32_t sm[2 * STAGE_U32];
    int g0 = blockIdx.x * PBM, bn = blockIdx.y;
    int n = g0 / T_DIM, t0 = g0 % T_DIM;
    const float* Aptr = A + (size_t)n * C_DIM * T_DIM + t0;
    const float* Bptr = W + (size_t)(bn * PBN) * C_DIM;

    int tid = threadIdx.x, lane = tid & 31, wid = tid >> 5;
    int wm = wid >> 1, wn = wid & 1, q = lane & 3, rG = lane >> 2;

    float acc[4][8][4];
    #pragma unroll
    for (int a = 0; a < 4; a++)
        #pragma unroll
        for (int b = 0; b < 8; b++)
            #pragma unroll
            for (int c = 0; c < 4; c++) acc[a][b][c] = 0.f;

    LdrAS la;
    LdrKM lb;
    la.ldg(Aptr, 0, tid);
    lb.ldg(Bptr, C_DIM, 0, tid);
    la.sts(sm, tid);
    lb.sts(sm + OPER_U32, tid);
    __syncthreads();

    for (int kt = 0; kt < NKT; kt++) {
        int p = kt & 1;
        if (kt + 1 < NKT) {
            la.ldg(Aptr, kt + 1, tid);
            lb.ldg(Bptr, C_DIM, kt + 1, tid);
        }
        const uint32_t* As = sm + p * STAGE_U32;
        mma_stage16(As, As + OPER_U32, acc, wm, wn, q, rG);
        if (kt + 1 < NKT) {
            uint32_t* d = sm + (p ^ 1) * STAGE_U32;
            la.sts(d, tid);
            lb.sts(d + OPER_U32, tid);
        }
        __syncthreads();
    }

    #pragma unroll
    for (int nt = 0; nt < 8; nt++) {
        int cb = bn * PBN + wn * 64 + nt * 8 + 2 * q;
        float b0 = bias[cb], b1 = bias[cb + 1];
        #pragma unroll
        for (int mt = 0; mt < 4; mt++) {
            int r = g0 + wm * 64 + mt * 16 + rG;
            *(float2*)&Cout[(size_t)r * C_DIM + cb] =
                make_float2(acc[mt][nt][0] + b0, acc[mt][nt][1] + b1);
            *(float2*)&Cout[(size_t)(r + 8) * C_DIM + cb] =
                make_float2(acc[mt][nt][2] + b0, acc[mt][nt][3] + b1);
        }
    }
}

// ---------------- GEMM: out-proj + bias + mask + residual ----------------------
// out[n][co][t] = (sum_c AO[g][c] * W_out[co][c] + b[co]) * mask[n][t] + x[n][co][t]
__global__ void __launch_bounds__(128, 2) gemm_out_f16(
    const float* __restrict__ W, const float* __restrict__ bias,
    const float* __restrict__ masks, const float* __restrict__ x,
    float* __restrict__ out)
{
    __shared__ uint32_t sm[2 * STAGE_U32];
    int g0 = blockIdx.x * PBM, bn = blockIdx.y;
    int n = g0 / T_DIM, t0 = g0 % T_DIM;
    const float* Aptr = g_AO + (size_t)g0 * C_DIM;
    const float* Bptr = W + (size_t)(bn * PBN) * C_DIM;

    int tid = threadIdx.x, lane = tid & 31, wid = tid >> 5;
    int wm = wid >> 1, wn = wid & 1, q = lane & 3, rG = lane >> 2;

    float acc[4][8][4];
    #pragma unroll
    for (int a = 0; a < 4; a++)
        #pragma unroll
        for (int b = 0; b < 8; b++)
            #pragma unroll
            for (int c = 0; c < 4; c++) acc[a][b][c] = 0.f;

    LdrKM la, lb;
    la.ldg(Aptr, C_DIM, 0, tid);
    lb.ldg(Bptr, C_DIM, 0, tid);
    la.sts(sm, tid);
    lb.sts(sm + OPER_U32, tid);
    __syncthreads();

    for (int kt = 0; kt < NKT; kt++) {
        int p = kt & 1;
        if (kt + 1 < NKT) {
            la.ldg(Aptr, C_DIM, kt + 1, tid);
            lb.ldg(Bptr, C_DIM, kt + 1, tid);
        }
        const uint32_t* As = sm + p * STAGE_U32;
        mma_stage16(As, As + OPER_U32, acc, wm, wn, q, rG);
        if (kt + 1 < NKT) {
            uint32_t* d = sm + (p ^ 1) * STAGE_U32;
            la.sts(d, tid);
            lb.sts(d + OPER_U32, tid);
        }
        __syncthreads();
    }

    #pragma unroll
    for (int mt = 0; mt < 4; mt++) {
        int r = wm * 64 + mt * 16 + rG;
        int tA = t0 + r;
        float mkA = masks[(size_t)n * T_DIM + tA];
        float mkB = masks[(size_t)n * T_DIM + tA + 8];
        #pragma unroll
        for (int nt = 0; nt < 8; nt++) {
            int co = bn * PBN + wn * 64 + nt * 8 + 2 * q;
            #pragma unroll
            for (int cj = 0; cj < 2; cj++) {
                float bb = bias[co + cj];
                size_t iA = ((size_t)(n * C_DIM + co + cj)) * T_DIM + tA;
                out[iA]     = (acc[mt][nt][cj]     + bb) * mkA + x[iA];
                out[iA + 8] = (acc[mt][nt][2 + cj] + bb) * mkB + x[iA + 8];
            }
        }
    }
}

// ---------------- attention via mma.sync (tf32): block per (chunk, head) -------
__global__ void __launch_bounds__(128) attn_mma(const float* __restrict__ masks)
{
    extern __shared__ uint32_t ash[];
    uint32_t* sQ = ash;
    uint32_t* sK = ash + ABUF;
    uint32_t* sV = ash + 2 * ABUF;
    uint32_t* sP = ash + 3 * ABUF;
    float* skm   = (float*)(ash + 4 * ABUF);

    int cb = blockIdx.x, h = blockIdx.y;
    int g0 = cb * CHUNK_SZ;
    int n = g0 / T_DIM, t0 = g0 % T_DIM;
    int tid = threadIdx.x, lane = tid & 31, w = tid >> 5;
    int q = lane & 3, rG = lane >> 2;

    if (tid < 64)
        skm[tid] = (masks[(size_t)n * T_DIM + t0 + tid] > 0.f) ? 0.f : NEG_INF;

    {
        int m = tid >> 1, dh = (tid & 1) * 32;
        const float* qp = g_QP + (size_t)(g0 + m) * C_DIM + h * DH;
        const float* kp = g_KP + (size_t)(g0 + m) * C_DIM + h * DH;
        #pragma unroll
        for (int i = 0; i < 4; i++) {
            int d0 = dh + i * 8;
            int slot0 = d0 >> 1;
            float4 v1 = *(const float4*)(qp + d0);
            float4 v2 = *(const float4*)(qp + d0 + 4);
            uint32_t* dst = sQ + ((uint32_t)slot0 * AP + m) * 2;
            *(uint2*)(dst)          = make_uint2(f2tf32(v1.x), f2tf32(v2.x));
            *(uint2*)(dst + AP * 2) = make_uint2(f2tf32(v1.y), f2tf32(v2.y));
            *(uint2*)(dst + AP * 4) = make_uint2(f2tf32(v1.z), f2tf32(v2.z));
            *(uint2*)(dst + AP * 6) = make_uint2(f2tf32(v1.w), f2tf32(v2.w));
            v1 = *(const float4*)(kp + d0);
            v2 = *(const float4*)(kp + d0 + 4);
            dst = sK + ((uint32_t)slot0 * AP + m) * 2;
            *(uint2*)(dst)          = make_uint2(f2tf32(v1.x), f2tf32(v2.x));
            *(uint2*)(dst + AP * 2) = make_uint2(f2tf32(v1.y), f2tf32(v2.y));
            *(uint2*)(dst + AP * 4) = make_uint2(f2tf32(v1.z), f2tf32(v2.z));
            *(uint2*)(dst + AP * 6) = make_uint2(f2tf32(v1.w), f2tf32(v2.w));
        }
    }
    {
        int tp = tid >> 2;
        int t  = (tp >> 2) * 8 + (tp & 3);
        const float* vp  = g_VP + (size_t)(g0 + t) * C_DIM + h * DH;
        const float* vp4 = vp + 4 * C_DIM;
        #pragma unroll
        for (int i = 0; i < 4; i++) {
            int d0 = ((tid & 3) * 4 + i) * 4;
            float4 v1 = *(const float4*)(vp + d0);
            float4 v2 = *(const float4*)(vp4 + d0);
            uint32_t* dst = sV + ((uint32_t)tp * AP + d0) * 2;
            *(uint4*)dst = make_uint4(f2tf32(v1.x), f2tf32(v2.x), f2tf32(v1.y), f2tf32(v2.y));
            *(uint4*)(dst + 4) = make_uint4(f2tf32(v1.z), f2tf32(v2.z), f2tf32(v1.w), f2tf32(v2.w));
        }
    }
    __syncthreads();

    int mA = w * 16 + rG;

    float s[8][4];
    #pragma unroll
    for (int nt = 0; nt < 8; nt++)
        #pragma unroll
        for (int j = 0; j < 4; j++) s[nt][j] = 0.f;
    #pragma unroll
    for (int ks = 0; ks < 8; ks++) {
        const uint32_t* Ab = sQ + ((uint32_t)(ks * 4 + q) * AP) * 2;
        const uint32_t* Bb = sK + ((uint32_t)(ks * 4 + q) * AP) * 2;
        uint2 aL = *(const uint2*)(Ab + mA * 2);
        uint2 aH = *(const uint2*)(Ab + (mA + 8) * 2);
        #pragma unroll
        for (int nt = 0; nt < 8; nt++) {
            uint2 bb = *(const uint2*)(Bb + (nt * 8 + rG) * 2);
            mma_tf32(s[nt], aL.x, aH.x, aL.y, aH.y, bb.x, bb.y);
        }
    }

    const float scale = 0.125f;
    float mxA = -3.4e38f, mxB = -3.4e38f;
    #pragma unroll
    for (int nt = 0; nt < 8; nt++) {
        int c0 = nt * 8 + 2 * q;
        float a0 = skm[c0], a1 = skm[c0 + 1];
        s[nt][0] = s[nt][0] * scale + a0;
        s[nt][1] = s[nt][1] * scale + a1;
        s[nt][2] = s[nt][2] * scale + a0;
        s[nt][3] = s[nt][3] * scale + a1;
        mxA = fmaxf(mxA, fmaxf(s[nt][0], s[nt][1]));
        mxB = fmaxf(mxB, fmaxf(s[nt][2], s[nt][3]));
    }
    mxA = fmaxf(mxA, __shfl_xor_sync(0xffffffffu, mxA, 1));
    mxA = fmaxf(mxA, __shfl_xor_sync(0xffffffffu, mxA, 2));
    mxB = fmaxf(mxB, __shfl_xor_sync(0xffffffffu, mxB, 1));
    mxB = fmaxf(mxB, __shfl_xor_sync(0xffffffffu, mxB, 2));
    float sA = 0.f, sB = 0.f;
    #pragma unroll
    for (int nt = 0; nt < 8; nt++) {
        s[nt][0] = __expf(s[nt][0] - mxA);
        s[nt][1] = __expf(s[nt][1] - mxA);
        s[nt][2] = __expf(s[nt][2] - mxB);
        s[nt][3] = __expf(s[nt][3] - mxB);
        sA += s[nt][0] + s[nt][1];
        sB += s[nt][2] + s[nt][3];
    }
    sA += __shfl_xor_sync(0xffffffffu, sA, 1);
    sA += __shfl_xor_sync(0xffffffffu, sA, 2);
    sB += __shfl_xor_sync(0xffffffffu, sB, 1);
    sB += __shfl_xor_sync(0xffffffffu, sB, 2);
    float iA = 1.f / sA, iB = 1.f / sB;

    #pragma unroll
    for (int nt = 0; nt < 8; nt++) {
        #pragma unroll
        for (int j = 0; j < 4; j++) {
            int kb = 2 * q + (j & 1);
            int slot = nt * 4 + (kb & 3);
            int kh = kb >> 2;
            int m = (j < 2) ? mA : (mA + 8);
            float val = s[nt][j] * ((j < 2) ? iA : iB);
            sP[((uint32_t)slot * AP + m) * 2 + kh] = f2tf32(val);
        }
    }
    __syncwarp();

    float o[8][4];
    #pragma unroll
    for (int nt = 0; nt < 8; nt++)
        #pragma unroll
        for (int j = 0; j < 4; j++) o[nt][j] = 0.f;
    #pragma unroll
    for (int ks = 0; ks < 8; ks++) {
        const uint32_t* Ab = sP + ((uint32_t)(ks * 4 + q) * AP) * 2;
        const uint32_t* Bb = sV + ((uint32_t)(ks * 4 + q) * AP) * 2;
        uint2 aL = *(const uint2*)(Ab + mA * 2);
        uint2 aH = *(const uint2*)(Ab + (mA + 8) * 2);
        #pragma unroll
        for (int nt = 0; nt < 8; nt++) {
            uint2 bb = *(const uint2*)(Bb + (nt * 8 + rG) * 2);
            mma_tf32(o[nt], aL.x, aH.x, aL.y, aH.y, bb.x, bb.y);
        }
    }

    float* aoA = g_AO + (size_t)(g0 + mA) * C_DIM + h * DH;
    float* aoB = g_AO + (size_t)(g0 + mA + 8) * C_DIM + h * DH;
    #pragma unroll
    for (int nt = 0; nt < 8; nt++) {
        int c0 = nt * 8 + 2 * q;
        *(float2*)(aoA + c0) = make_float2(o[nt][0], o[nt][1]);
        *(float2*)(aoB + c0) = make_float2(o[nt][2], o[nt][3]);
    }
}

// ---------------- InstanceNorm1d over T per (n,c) row ---------------------------
__global__ void __launch_bounds__(256) inorm_kernel(float* __restrict__ out)
{
    __shared__ float red[18];
    int row = blockIdx.x;
    float* p = out + (size_t)row * T_DIM;
    int tid = threadIdx.x;

    float4 v[4];
    float s = 0.f, s2 = 0.f;
    #pragma unroll
    for (int i = 0; i < 4; i++) {
        v[i] = *(const float4*)(p + i * 1024 + tid * 4);
        s  += v[i].x + v[i].y + v[i].z + v[i].w;
        s2 += v[i].x * v[i].x + v[i].y * v[i].y + v[i].z * v[i].z + v[i].w * v[i].w;
    }
    #pragma unroll
    for (int o = 16; o; o >>= 1) {
        s  += __shfl_xor_sync(0xffffffffu, s,  o);
        s2 += __shfl_xor_sync(0xffffffffu, s2, o);
    }
    int warp = tid >> 5, lane = tid & 31;
    if (lane == 0) { red[warp] = s; red[8 + warp] = s2; }
    __syncthreads();
    if (warp == 0) {
        float a  = (lane < 8) ? red[lane]     : 0.f;
        float a2 = (lane < 8) ? red[8 + lane] : 0.f;
        #pragma unroll
        for (int o = 4; o; o >>= 1) {
            a  += __shfl_xor_sync(0xffffffffu, a,  o);
            a2 += __shfl_xor_sync(0xffffffffu, a2, o);
        }
        if (lane == 0) { red[16] = a; red[17] = a2; }
    }
    __syncthreads();
    float mu  = red[16] * (1.f / T_DIM);
    float var = red[17] * (1.f / T_DIM) - mu * mu;
    float rs  = rsqrtf(var + 1e-5f);
    #pragma unroll
    for (int i = 0; i < 4; i++) {
        float4 r;
        r.x = (v[i].x - mu) * rs; r.y = (v[i].y - mu) * rs;
        r.z = (v[i].z - mu) * rs; r.w = (v[i].w - mu) * rs;
        *(float4*)(p + i * 1024 + tid * 4) = r;
    }
}

// ---------------- launch ---------------------------------------------------------
extern "C" void kernel_launch(void* const* d_in, const int* in_sizes, int n_in,
                              void* d_out, int out_size)
{
    const float* x     = (const float*)d_in[0];
    const float* q     = (const float*)d_in[1];
    const float* k     = (const float*)d_in[2];
    const float* v     = (const float*)d_in[3];
    const float* masks = (const float*)d_in[4];
    const float* W_in  = (const float*)d_in[5];
    const float* b_in  = (const float*)d_in[6];
    const float* W_out = (const float*)d_in[7];
    const float* b_out = (const float*)d_in[8];
    float* out = (float*)d_out;

    float *QP, *KP, *VP;
    cudaGetSymbolAddress((void**)&QP, g_QP);
    cudaGetSymbolAddress((void**)&KP, g_KP);
    cudaGetSymbolAddress((void**)&VP, g_VP);

    cudaFuncSetAttribute(attn_mma, cudaFuncAttributeMaxDynamicSharedMemorySize,
                         ASMEM_BYTES);

    dim3 gg(NTOK / PBM, C_DIM / PBN);   // (128, 4)
    // W_in rows: [0:512)=Wq, [512:1024)=Wk, [1024:1536)=Wv, each [co][c]
    gemm_proj_f16<<<gg, 128>>>(q, W_in,                         b_in,        QP);
    gemm_proj_f16<<<gg, 128>>>(k, W_in + (size_t)512  * C_DIM,  b_in + 512,  KP);
    gemm_proj_f16<<<gg, 128>>>(v, W_in + (size_t)1024 * C_DIM,  b_in + 1024, VP);

    attn_mma<<<dim3(NTOK / CHUNK_SZ, H_HEADS), 128, ASMEM_BYTES>>>(masks);

    gemm_out_f16<<<gg, 128>>>(W_out, b_out, masks, x, out);

    inorm_kernel<<<N_BATCH * C_DIM, 256>>>(out);
}

// round 6
// speedup vs baseline: 3.5133x; 1.0284x over previous
#include <cuda_runtime.h>
#include <cuda_bf16.h>
#include <cstdint>

#define N_BATCH 4
#define C_DIM   512
#define T_DIM   4096
#define NTOK    (N_BATCH * T_DIM)   // 16384
#define H_HEADS 8
#define DH      64
#define CHUNK_SZ 64
#define NEG_INF (-1e9f)

// ---------------- fp16 GEMM tiling -------------------------------------------
#define PBM 128
#define PBN 128
#define NKT (C_DIM / 32)       // 16
#define GP  132                // uint2 pitch; 132 % 16 == 4 -> frag LDS conflict-free
#define OPER_U32 (8 * GP * 2)
#define STAGE_U32 (2 * OPER_U32)

// ---------------- fp16 attention tiling ---------------------------------------
#define AP2 68                 // uint2 pitch (64 + pad4)
#define ABUF2 (16 * AP2 * 2)   // one 64x64 f16 buffer in u32: 2176
#define ASMEM2 ((3 * ABUF2 + 64) * 4)   // Q(/P), K, V + mask = 26368 B

// ---------------- scratch ------------------------------------------------------
__device__ float g_QP[(size_t)NTOK * C_DIM];
__device__ float g_KP[(size_t)NTOK * C_DIM];
__device__ float g_VP[(size_t)NTOK * C_DIM];
__device__ float g_AO[(size_t)NTOK * C_DIM];

// ---------------- helpers ------------------------------------------------------
__device__ __forceinline__ uint32_t pack_f16x2(float lo, float hi) {
    uint32_t r;
    asm("cvt.rn.f16x2.f32 %0, %1, %2;" : "=r"(r) : "f"(hi), "f"(lo));
    return r;
}

__device__ __forceinline__ void mma_f16(float* c,
                                        uint32_t a0, uint32_t a1, uint32_t a2, uint32_t a3,
                                        uint32_t b0, uint32_t b1) {
    asm volatile(
        "mma.sync.aligned.m16n8k16.row.col.f32.f16.f16.f32 "
        "{%0,%1,%2,%3}, {%4,%5,%6,%7}, {%8,%9}, {%0,%1,%2,%3};\n"
        : "+f"(c[0]), "+f"(c[1]), "+f"(c[2]), "+f"(c[3])
        : "r"(a0), "r"(a1), "r"(a2), "r"(a3), "r"(b0), "r"(b1));
}

// ======================= fp16 GEMM building blocks =============================
struct LdrAS {
    float4 lo[2][2], hi[2][2];
    __device__ __forceinline__ void ldg(const float* base, int kt, int tid) {
        int w = tid >> 5, m0 = (tid & 31) * 4;
        #pragma unroll
        for (int si = 0; si < 2; si++) {
            int s = 2 * w + si;
            #pragma unroll
            for (int kh = 0; kh < 2; kh++) {
                int kw = (s >> 2) * 8 + kh * 4 + (s & 3);
                const float* p = base + (size_t)(kt * 32 + 2 * kw) * T_DIM + m0;
                lo[si][kh] = *(const float4*)p;
                hi[si][kh] = *(const float4*)(p + T_DIM);
            }
        }
    }
    __device__ __forceinline__ void sts(uint32_t* buf, int tid) {
        int w = tid >> 5, m0 = (tid & 31) * 4;
        #pragma unroll
        for (int si = 0; si < 2; si++) {
            int s = 2 * w + si;
            uint32_t wd[2][4];
            #pragma unroll
            for (int kh = 0; kh < 2; kh++) {
                const float* l = (const float*)&lo[si][kh];
                const float* h = (const float*)&hi[si][kh];
                #pragma unroll
                for (int j = 0; j < 4; j++) wd[kh][j] = pack_f16x2(l[j], h[j]);
            }
            uint32_t* d = buf + ((uint32_t)s * GP + m0) * 2;
            *(uint4*)d       = make_uint4(wd[0][0], wd[1][0], wd[0][1], wd[1][1]);
            *(uint4*)(d + 4) = make_uint4(wd[0][2], wd[1][2], wd[0][3], wd[1][3]);
        }
    }
};

struct LdrKM {
    float4 v[4][2];
    __device__ __forceinline__ void ldg(const float* base, int ld, int kt, int tid) {
        int mb = tid >> 2, kq = tid & 3;
        #pragma unroll
        for (int i = 0; i < 4; i++) {
            const float* p = base + (size_t)(mb + 32 * i) * ld + kt * 32 + kq * 8;
            v[i][0] = *(const float4*)p;
            v[i][1] = *(const float4*)(p + 4);
        }
    }
    __device__ __forceinline__ void sts(uint32_t* buf, int tid) {
        int mb = tid >> 2, kq = tid & 3;
        int sb = (kq >> 1) * 4, kh = kq & 1;
        #pragma unroll
        for (int i = 0; i < 4; i++) {
            int n = mb + 32 * i;
            const float* f = (const float*)&v[i][0];
            #pragma unroll
            for (int j = 0; j < 4; j++)
                buf[((uint32_t)(sb + j) * GP + n) * 2 + kh] = pack_f16x2(f[2 * j], f[2 * j + 1]);
        }
    }
};

__device__ __forceinline__ void mma_stage16(const uint32_t* As, const uint32_t* Bs,
                                            float acc[4][8][4], int wm, int wn,
                                            int q, int rG) {
    #pragma unroll
    for (int ks = 0; ks < 2; ks++) {
        const uint32_t* Ab = As + ((uint32_t)(ks * 4 + q) * GP) * 2;
        const uint32_t* Bb = Bs + ((uint32_t)(ks * 4 + q) * GP) * 2;
        uint2 aL[4], aH[4];
        #pragma unroll
        for (int mt = 0; mt < 4; mt++) {
            int m = wm * 64 + mt * 16 + rG;
            aL[mt] = *(const uint2*)(Ab + m * 2);
            aH[mt] = *(const uint2*)(Ab + (m + 8) * 2);
        }
        #pragma unroll
        for (int nt = 0; nt < 8; nt++) {
            uint2 bb = *(const uint2*)(Bb + (wn * 64 + nt * 8 + rG) * 2);
            #pragma unroll
            for (int mt = 0; mt < 4; mt++)
                mma_f16(acc[mt][nt], aL[mt].x, aH[mt].x, aL[mt].y, aH[mt].y, bb.x, bb.y);
        }
    }
}

// ---------------- GEMM: projections (fp16 MMA) --------------------------------
__global__ void __launch_bounds__(128, 2) gemm_proj_f16(
    const float* __restrict__ A, const float* __restrict__ W,
    const float* __restrict__ bias, float* __restrict__ Cout)
{
    __shared__ uint32_t sm[2 * STAGE_U32];
    int g0 = blockIdx.x * PBM, bn = blockIdx.y;
    int n = g0 / T_DIM, t0 = g0 % T_DIM;
    const float* Aptr = A + (size_t)n * C_DIM * T_DIM + t0;
    const float* Bptr = W + (size_t)(bn * PBN) * C_DIM;

    int tid = threadIdx.x, lane = tid & 31, wid = tid >> 5;
    int wm = wid >> 1, wn = wid & 1, q = lane & 3, rG = lane >> 2;

    float acc[4][8][4];
    #pragma unroll
    for (int a = 0; a < 4; a++)
        #pragma unroll
        for (int b = 0; b < 8; b++)
            #pragma unroll
            for (int c = 0; c < 4; c++) acc[a][b][c] = 0.f;

    LdrAS la;
    LdrKM lb;
    la.ldg(Aptr, 0, tid);
    lb.ldg(Bptr, C_DIM, 0, tid);
    la.sts(sm, tid);
    lb.sts(sm + OPER_U32, tid);
    __syncthreads();

    for (int kt = 0; kt < NKT; kt++) {
        int p = kt & 1;
        if (kt + 1 < NKT) {
            la.ldg(Aptr, kt + 1, tid);
            lb.ldg(Bptr, C_DIM, kt + 1, tid);
        }
        const uint32_t* As = sm + p * STAGE_U32;
        mma_stage16(As, As + OPER_U32, acc, wm, wn, q, rG);
        if (kt + 1 < NKT) {
            uint32_t* d = sm + (p ^ 1) * STAGE_U32;
            la.sts(d, tid);
            lb.sts(d + OPER_U32, tid);
        }
        __syncthreads();
    }

    #pragma unroll
    for (int nt = 0; nt < 8; nt++) {
        int cb = bn * PBN + wn * 64 + nt * 8 + 2 * q;
        float b0 = bias[cb], b1 = bias[cb + 1];
        #pragma unroll
        for (int mt = 0; mt < 4; mt++) {
            int r = g0 + wm * 64 + mt * 16 + rG;
            *(float2*)&Cout[(size_t)r * C_DIM + cb] =
                make_float2(acc[mt][nt][0] + b0, acc[mt][nt][1] + b1);
            *(float2*)&Cout[(size_t)(r + 8) * C_DIM + cb] =
                make_float2(acc[mt][nt][2] + b0, acc[mt][nt][3] + b1);
        }
    }
}

// ---------------- GEMM: out-proj + bias + mask + residual ----------------------
__global__ void __launch_bounds__(128, 2) gemm_out_f16(
    const float* __restrict__ W, const float* __restrict__ bias,
    const float* __restrict__ masks, const float* __restrict__ x,
    float* __restrict__ out)
{
    __shared__ uint32_t sm[2 * STAGE_U32];
    int g0 = blockIdx.x * PBM, bn = blockIdx.y;
    int n = g0 / T_DIM, t0 = g0 % T_DIM;
    const float* Aptr = g_AO + (size_t)g0 * C_DIM;
    const float* Bptr = W + (size_t)(bn * PBN) * C_DIM;

    int tid = threadIdx.x, lane = tid & 31, wid = tid >> 5;
    int wm = wid >> 1, wn = wid & 1, q = lane & 3, rG = lane >> 2;

    float acc[4][8][4];
    #pragma unroll
    for (int a = 0; a < 4; a++)
        #pragma unroll
        for (int b = 0; b < 8; b++)
            #pragma unroll
            for (int c = 0; c < 4; c++) acc[a][b][c] = 0.f;

    LdrKM la, lb;
    la.ldg(Aptr, C_DIM, 0, tid);
    lb.ldg(Bptr, C_DIM, 0, tid);
    la.sts(sm, tid);
    lb.sts(sm + OPER_U32, tid);
    __syncthreads();

    for (int kt = 0; kt < NKT; kt++) {
        int p = kt & 1;
        if (kt + 1 < NKT) {
            la.ldg(Aptr, C_DIM, kt + 1, tid);
            lb.ldg(Bptr, C_DIM, kt + 1, tid);
        }
        const uint32_t* As = sm + p * STAGE_U32;
        mma_stage16(As, As + OPER_U32, acc, wm, wn, q, rG);
        if (kt + 1 < NKT) {
            uint32_t* d = sm + (p ^ 1) * STAGE_U32;
            la.sts(d, tid);
            lb.sts(d + OPER_U32, tid);
        }
        __syncthreads();
    }

    #pragma unroll
    for (int mt = 0; mt < 4; mt++) {
        int r = wm * 64 + mt * 16 + rG;
        int tA = t0 + r;
        float mkA = masks[(size_t)n * T_DIM + tA];
        float mkB = masks[(size_t)n * T_DIM + tA + 8];
        #pragma unroll
        for (int nt = 0; nt < 8; nt++) {
            int co = bn * PBN + wn * 64 + nt * 8 + 2 * q;
            #pragma unroll
            for (int cj = 0; cj < 2; cj++) {
                float bb = bias[co + cj];
                size_t iA = ((size_t)(n * C_DIM + co + cj)) * T_DIM + tA;
                out[iA]     = (acc[mt][nt][cj]     + bb) * mkA + x[iA];
                out[iA + 8] = (acc[mt][nt][2 + cj] + bb) * mkB + x[iA + 8];
            }
        }
    }
}

// ---------------- attention (fp16 MMA): block per (chunk, head) ----------------
// smem buffers in GEMM-style f16x2 word layout:
//   word(m, kw) = f16x2(src[m][2kw], src[m][2kw+1]), kw 0..31
//   slot = (kw>>3)*4 + (kw&3), kh = (kw>>2)&1; u32 addr = (slot*AP2 + m)*2 + kh
__global__ void __launch_bounds__(128) attn_f16(const float* __restrict__ masks)
{
    extern __shared__ uint32_t ash[];
    uint32_t* sQ = ash;                 // Q, later reused for P (warp-local rows)
    uint32_t* sK = ash + ABUF2;
    uint32_t* sV = ash + 2 * ABUF2;     // V^T: rows = d, k = token
    float* skm   = (float*)(ash + 3 * ABUF2);

    int cb = blockIdx.x, h = blockIdx.y;
    int g0 = cb * CHUNK_SZ;
    int n = g0 / T_DIM, t0 = g0 % T_DIM;
    int tid = threadIdx.x, lane = tid & 31, w = tid >> 5;
    int q = lane & 3, rG = lane >> 2;

    if (tid < 64)
        skm[tid] = (masks[(size_t)n * T_DIM + t0 + tid] > 0.f) ? 0.f : NEG_INF;

    // ---- load Q, K (rows = tokens) ----
    {
        int m = tid >> 1, dh = (tid & 1) * 32;
        const float* qp = g_QP + (size_t)(g0 + m) * C_DIM + h * DH + dh;
        const float* kp = g_KP + (size_t)(g0 + m) * C_DIM + h * DH + dh;
        #pragma unroll
        for (int i = 0; i < 4; i++) {
            int d0 = dh + i * 8;
            int sb = (d0 >> 4) * 4;
            int kh = (d0 >> 3) & 1;
            float4 v1 = *(const float4*)(qp + i * 8);
            float4 v2 = *(const float4*)(qp + i * 8 + 4);
            sQ[((uint32_t)(sb + 0) * AP2 + m) * 2 + kh] = pack_f16x2(v1.x, v1.y);
            sQ[((uint32_t)(sb + 1) * AP2 + m) * 2 + kh] = pack_f16x2(v1.z, v1.w);
            sQ[((uint32_t)(sb + 2) * AP2 + m) * 2 + kh] = pack_f16x2(v2.x, v2.y);
            sQ[((uint32_t)(sb + 3) * AP2 + m) * 2 + kh] = pack_f16x2(v2.z, v2.w);
            v1 = *(const float4*)(kp + i * 8);
            v2 = *(const float4*)(kp + i * 8 + 4);
            sK[((uint32_t)(sb + 0) * AP2 + m) * 2 + kh] = pack_f16x2(v1.x, v1.y);
            sK[((uint32_t)(sb + 1) * AP2 + m) * 2 + kh] = pack_f16x2(v1.z, v1.w);
            sK[((uint32_t)(sb + 2) * AP2 + m) * 2 + kh] = pack_f16x2(v2.x, v2.y);
            sK[((uint32_t)(sb + 3) * AP2 + m) * 2 + kh] = pack_f16x2(v2.z, v2.w);
        }
    }
    // ---- load V^T (rows = d, k = token; word = (V[2kw][d], V[2kw+1][d])) ----
    {
        int kwv = tid >> 2;                  // token pair 0..31
        int d0  = (tid & 3) * 16;
        const float* r0 = g_VP + (size_t)(g0 + 2 * kwv) * C_DIM + h * DH + d0;
        const float* r1 = r0 + C_DIM;
        int slot = (kwv >> 3) * 4 + (kwv & 3);
        int kh = (kwv >> 2) & 1;
        uint32_t* dst = sV + ((uint32_t)slot * AP2 + d0) * 2 + kh;
        #pragma unroll
        for (int j = 0; j < 16; j += 4) {
            float4 a = *(const float4*)(r0 + j);
            float4 b = *(const float4*)(r1 + j);
            dst[(j + 0) * 2] = pack_f16x2(a.x, b.x);
            dst[(j + 1) * 2] = pack_f16x2(a.y, b.y);
            dst[(j + 2) * 2] = pack_f16x2(a.z, b.z);
            dst[(j + 3) * 2] = pack_f16x2(a.w, b.w);
        }
    }
    __syncthreads();

    int mA = w * 16 + rG;

    // ---- S = Q K^T ----
    float s[8][4];
    #pragma unroll
    for (int nt = 0; nt < 8; nt++)
        #pragma unroll
        for (int j = 0; j < 4; j++) s[nt][j] = 0.f;
    #pragma unroll
    for (int ks = 0; ks < 4; ks++) {
        const uint32_t* Ab = sQ + ((uint32_t)(ks * 4 + q) * AP2) * 2;
        const uint32_t* Bb = sK + ((uint32_t)(ks * 4 + q) * AP2) * 2;
        uint2 aL = *(const uint2*)(Ab + mA * 2);
        uint2 aH = *(const uint2*)(Ab + (mA + 8) * 2);
        #pragma unroll
        for (int nt = 0; nt < 8; nt++) {
            uint2 bb = *(const uint2*)(Bb + (nt * 8 + rG) * 2);
            mma_f16(s[nt], aL.x, aH.x, aL.y, aH.y, bb.x, bb.y);
        }
    }

    // ---- softmax in registers ----
    const float scale = 0.125f;
    float mxA = -3.4e38f, mxB = -3.4e38f;
    #pragma unroll
    for (int nt = 0; nt < 8; nt++) {
        int c0 = nt * 8 + 2 * q;
        float a0 = skm[c0], a1 = skm[c0 + 1];
        s[nt][0] = s[nt][0] * scale + a0;
        s[nt][1] = s[nt][1] * scale + a1;
        s[nt][2] = s[nt][2] * scale + a0;
        s[nt][3] = s[nt][3] * scale + a1;
        mxA = fmaxf(mxA, fmaxf(s[nt][0], s[nt][1]));
        mxB = fmaxf(mxB, fmaxf(s[nt][2], s[nt][3]));
    }
    mxA = fmaxf(mxA, __shfl_xor_sync(0xffffffffu, mxA, 1));
    mxA = fmaxf(mxA, __shfl_xor_sync(0xffffffffu, mxA, 2));
    mxB = fmaxf(mxB, __shfl_xor_sync(0xffffffffu, mxB, 1));
    mxB = fmaxf(mxB, __shfl_xor_sync(0xffffffffu, mxB, 2));
    float sA = 0.f, sB = 0.f;
    #pragma unroll
    for (int nt = 0; nt < 8; nt++) {
        s[nt][0] = __expf(s[nt][0] - mxA);
        s[nt][1] = __expf(s[nt][1] - mxA);
        s[nt][2] = __expf(s[nt][2] - mxB);
        s[nt][3] = __expf(s[nt][3] - mxB);
        sA += s[nt][0] + s[nt][1];
        sB += s[nt][2] + s[nt][3];
    }
    sA += __shfl_xor_sync(0xffffffffu, sA, 1);
    sA += __shfl_xor_sync(0xffffffffu, sA, 2);
    sB += __shfl_xor_sync(0xffffffffu, sB, 1);
    sB += __shfl_xor_sync(0xffffffffu, sB, 2);
    float iA = 1.f / sA, iB = 1.f / sB;

    // ---- write P into sQ (warp-local rows; lane-private round-trip) ----
    #pragma unroll
    for (int nt = 0; nt < 8; nt++) {
        int kw = nt * 4 + q;                  // key pair = (2kw, 2kw+1) = (c0, c0+1)
        int slot = (kw >> 3) * 4 + (kw & 3);
        int kh = (kw >> 2) & 1;
        sQ[((uint32_t)slot * AP2 + mA) * 2 + kh]       = pack_f16x2(s[nt][0] * iA, s[nt][1] * iA);
        sQ[((uint32_t)slot * AP2 + mA + 8) * 2 + kh]   = pack_f16x2(s[nt][2] * iB, s[nt][3] * iB);
    }
    __syncwarp();

    // ---- O = P V ----
    float o[8][4];
    #pragma unroll
    for (int nt = 0; nt < 8; nt++)
        #pragma unroll
        for (int j = 0; j < 4; j++) o[nt][j] = 0.f;
    #pragma unroll
    for (int ks = 0; ks < 4; ks++) {
        const uint32_t* Ab = sQ + ((uint32_t)(ks * 4 + q) * AP2) * 2;
        const uint32_t* Bb = sV + ((uint32_t)(ks * 4 + q) * AP2) * 2;
        uint2 aL = *(const uint2*)(Ab + mA * 2);
        uint2 aH = *(const uint2*)(Ab + (mA + 8) * 2);
        #pragma unroll
        for (int nt = 0; nt < 8; nt++) {
            uint2 bb = *(const uint2*)(Bb + (nt * 8 + rG) * 2);
            mma_f16(o[nt], aL.x, aH.x, aL.y, aH.y, bb.x, bb.y);
        }
    }

    // ---- store O to g_AO[g][co] ----
    float* aoA = g_AO + (size_t)(g0 + mA) * C_DIM + h * DH;
    float* aoB = g_AO + (size_t)(g0 + mA + 8) * C_DIM + h * DH;
    #pragma unroll
    for (int nt = 0; nt < 8; nt++) {
        int c0 = nt * 8 + 2 * q;
        *(float2*)(aoA + c0) = make_float2(o[nt][0], o[nt][1]);
        *(float2*)(aoB + c0) = make_float2(o[nt][2], o[nt][3]);
    }
}

// ---------------- InstanceNorm1d over T per (n,c) row ---------------------------
__global__ void __launch_bounds__(256) inorm_kernel(float* __restrict__ out)
{
    __shared__ float red[18];
    int row = blockIdx.x;
    float* p = out + (size_t)row * T_DIM;
    int tid = threadIdx.x;

    float4 v[4];
    float s = 0.f, s2 = 0.f;
    #pragma unroll
    for (int i = 0; i < 4; i++) {
        v[i] = *(const float4*)(p + i * 1024 + tid * 4);
        s  += v[i].x + v[i].y + v[i].z + v[i].w;
        s2 += v[i].x * v[i].x + v[i].y * v[i].y + v[i].z * v[i].z + v[i].w * v[i].w;
    }
    #pragma unroll
    for (int o = 16; o; o >>= 1) {
        s  += __shfl_xor_sync(0xffffffffu, s,  o);
        s2 += __shfl_xor_sync(0xffffffffu, s2, o);
    }
    int warp = tid >> 5, lane = tid & 31;
    if (lane == 0) { red[warp] = s; red[8 + warp] = s2; }
    __syncthreads();
    if (warp == 0) {
        float a  = (lane < 8) ? red[lane]     : 0.f;
        float a2 = (lane < 8) ? red[8 + lane] : 0.f;
        #pragma unroll
        for (int o = 4; o; o >>= 1) {
            a  += __shfl_xor_sync(0xffffffffu, a,  o);
            a2 += __shfl_xor_sync(0xffffffffu, a2, o);
        }
        if (lane == 0) { red[16] = a; red[17] = a2; }
    }
    __syncthreads();
    float mu  = red[16] * (1.f / T_DIM);
    float var = red[17] * (1.f / T_DIM) - mu * mu;
    float rs  = rsqrtf(var + 1e-5f);
    #pragma unroll
    for (int i = 0; i < 4; i++) {
        float4 r;
        r.x = (v[i].x - mu) * rs; r.y = (v[i].y - mu) * rs;
        r.z = (v[i].z - mu) * rs; r.w = (v[i].w - mu) * rs;
        *(float4*)(p + i * 1024 + tid * 4) = r;
    }
}

// ---------------- launch ---------------------------------------------------------
extern "C" void kernel_launch(void* const* d_in, const int* in_sizes, int n_in,
                              void* d_out, int out_size)
{
    const float* x     = (const float*)d_in[0];
    const float* q     = (const float*)d_in[1];
    const float* k     = (const float*)d_in[2];
    const float* v     = (const float*)d_in[3];
    const float* masks = (const float*)d_in[4];
    const float* W_in  = (const float*)d_in[5];
    const float* b_in  = (const float*)d_in[6];
    const float* W_out = (const float*)d_in[7];
    const float* b_out = (const float*)d_in[8];
    float* out = (float*)d_out;

    float *QP, *KP, *VP;
    cudaGetSymbolAddress((void**)&QP, g_QP);
    cudaGetSymbolAddress((void**)&KP, g_KP);
    cudaGetSymbolAddress((void**)&VP, g_VP);

    cudaFuncSetAttribute(attn_f16, cudaFuncAttributeMaxDynamicSharedMemorySize,
                         ASMEM2);

    dim3 gg(NTOK / PBM, C_DIM / PBN);   // (128, 4)
    gemm_proj_f16<<<gg, 128>>>(q, W_in,                         b_in,        QP);
    gemm_proj_f16<<<gg, 128>>>(k, W_in + (size_t)512  * C_DIM,  b_in + 512,  KP);
    gemm_proj_f16<<<gg, 128>>>(v, W_in + (size_t)1024 * C_DIM,  b_in + 1024, VP);

    attn_f16<<<dim3(NTOK / CHUNK_SZ, H_HEADS), 128, ASMEM2>>>(masks);

    gemm_out_f16<<<gg, 128>>>(W_out, b_out, masks, x, out);

    inorm_kernel<<<N_BATCH * C_DIM, 256>>>(out);
}

// round 7
// speedup vs baseline: 4.2331x; 1.2049x over previous
#include <cuda_runtime.h>
#include <cuda_bf16.h>
#include <cstdint>

#define N_BATCH 4
#define C_DIM   512
#define C_W     256            // C_DIM/2 f16x2 words per row
#define T_DIM   4096
#define NTOK    (N_BATCH * T_DIM)   // 16384
#define H_HEADS 8
#define DH      64
#define CHUNK_SZ 64
#define NEG_INF (-1e9f)

// ---------------- fp16 GEMM tiling -------------------------------------------
#define PBM 128
#define PBN 128
#define NKT (C_DIM / 32)       // 16
#define GP  132                // uint2 pitch; 132 % 16 == 4 -> frag LDS conflict-free
#define OPER_U32 (8 * GP * 2)
#define STAGE_U32 (2 * OPER_U32)

// ---------------- fp16 attention tiling ---------------------------------------
#define AP2 68                 // uint2 pitch (64 + pad4)
#define ABUF2 (16 * AP2 * 2)   // one 64x64 f16 buffer in u32: 2176
#define ASMEM2 ((3 * ABUF2 + 64) * 4)   // Q(/P), K, V + mask = 26368 B

// ---------------- scratch (fp16 packed as u32 words) ---------------------------
__device__ uint32_t g_QP16[(size_t)NTOK * C_W];
__device__ uint32_t g_KP16[(size_t)NTOK * C_W];
__device__ uint32_t g_VP16[(size_t)NTOK * C_W];
__device__ uint32_t g_AO16[(size_t)NTOK * C_W];

// ---------------- helpers ------------------------------------------------------
__device__ __forceinline__ uint32_t pack_f16x2(float lo, float hi) {
    uint32_t r;
    asm("cvt.rn.f16x2.f32 %0, %1, %2;" : "=r"(r) : "f"(hi), "f"(lo));
    return r;
}

__device__ __forceinline__ uint32_t prmt_u32(uint32_t a, uint32_t b, uint32_t sel) {
    uint32_t r;
    asm("prmt.b32 %0, %1, %2, %3;" : "=r"(r) : "r"(a), "r"(b), "r"(sel));
    return r;
}

__device__ __forceinline__ void mma_f16(float* c,
                                        uint32_t a0, uint32_t a1, uint32_t a2, uint32_t a3,
                                        uint32_t b0, uint32_t b1) {
    asm volatile(
        "mma.sync.aligned.m16n8k16.row.col.f32.f16.f16.f32 "
        "{%0,%1,%2,%3}, {%4,%5,%6,%7}, {%8,%9}, {%0,%1,%2,%3};\n"
        : "+f"(c[0]), "+f"(c[1]), "+f"(c[2]), "+f"(c[3])
        : "r"(a0), "r"(a1), "r"(a2), "r"(a3), "r"(b0), "r"(b1));
}

// ======================= fp16 GEMM building blocks =============================
// A loader, k-strided fp32 source (inputs [c][t])
struct LdrAS {
    float4 lo[2][2], hi[2][2];
    __device__ __forceinline__ void ldg(const float* base, int kt, int tid) {
        int w = tid >> 5, m0 = (tid & 31) * 4;
        #pragma unroll
        for (int si = 0; si < 2; si++) {
            int s = 2 * w + si;
            #pragma unroll
            for (int kh = 0; kh < 2; kh++) {
                int kw = (s >> 2) * 8 + kh * 4 + (s & 3);
                const float* p = base + (size_t)(kt * 32 + 2 * kw) * T_DIM + m0;
                lo[si][kh] = *(const float4*)p;
                hi[si][kh] = *(const float4*)(p + T_DIM);
            }
        }
    }
    __device__ __forceinline__ void sts(uint32_t* buf, int tid) {
        int w = tid >> 5, m0 = (tid & 31) * 4;
        #pragma unroll
        for (int si = 0; si < 2; si++) {
            int s = 2 * w + si;
            uint32_t wd[2][4];
            #pragma unroll
            for (int kh = 0; kh < 2; kh++) {
                const float* l = (const float*)&lo[si][kh];
                const float* h = (const float*)&hi[si][kh];
                #pragma unroll
                for (int j = 0; j < 4; j++) wd[kh][j] = pack_f16x2(l[j], h[j]);
            }
            uint32_t* d = buf + ((uint32_t)s * GP + m0) * 2;
            *(uint4*)d       = make_uint4(wd[0][0], wd[1][0], wd[0][1], wd[1][1]);
            *(uint4*)(d + 4) = make_uint4(wd[0][2], wd[1][2], wd[0][3], wd[1][3]);
        }
    }
};

// k-contiguous fp32 loader (weights [n][k])
struct LdrKM {
    float4 v[4][2];
    __device__ __forceinline__ void ldg(const float* base, int ld, int kt, int tid) {
        int mb = tid >> 2, kq = tid & 3;
        #pragma unroll
        for (int i = 0; i < 4; i++) {
            const float* p = base + (size_t)(mb + 32 * i) * ld + kt * 32 + kq * 8;
            v[i][0] = *(const float4*)p;
            v[i][1] = *(const float4*)(p + 4);
        }
    }
    __device__ __forceinline__ void sts(uint32_t* buf, int tid) {
        int mb = tid >> 2, kq = tid & 3;
        int sb = (kq >> 1) * 4, kh = kq & 1;
        #pragma unroll
        for (int i = 0; i < 4; i++) {
            int n = mb + 32 * i;
            const float* f = (const float*)&v[i][0];
            #pragma unroll
            for (int j = 0; j < 4; j++)
                buf[((uint32_t)(sb + j) * GP + n) * 2 + kh] = pack_f16x2(f[2 * j], f[2 * j + 1]);
        }
    }
};

// k-contiguous fp16 loader (AO16 [m][kw]) — pure copy, no cvt
struct LdrA16 {
    uint4 v[4];
    __device__ __forceinline__ void ldg(const uint32_t* base, int kt, int tid) {
        int mb = tid >> 2, kq = tid & 3;
        #pragma unroll
        for (int i = 0; i < 4; i++)
            v[i] = *(const uint4*)(base + (size_t)(mb + 32 * i) * C_W + kt * 16 + kq * 4);
    }
    __device__ __forceinline__ void sts(uint32_t* buf, int tid) {
        int mb = tid >> 2, kq = tid & 3;
        int sb = (kq >> 1) * 4, kh = kq & 1;
        #pragma unroll
        for (int i = 0; i < 4; i++) {
            int m = mb + 32 * i;
            const uint32_t* w = (const uint32_t*)&v[i];
            #pragma unroll
            for (int j = 0; j < 4; j++)
                buf[((uint32_t)(sb + j) * GP + m) * 2 + kh] = w[j];
        }
    }
};

__device__ __forceinline__ void mma_stage16(const uint32_t* As, const uint32_t* Bs,
                                            float acc[4][8][4], int wm, int wn,
                                            int q, int rG) {
    #pragma unroll
    for (int ks = 0; ks < 2; ks++) {
        const uint32_t* Ab = As + ((uint32_t)(ks * 4 + q) * GP) * 2;
        const uint32_t* Bb = Bs + ((uint32_t)(ks * 4 + q) * GP) * 2;
        uint2 aL[4], aH[4];
        #pragma unroll
        for (int mt = 0; mt < 4; mt++) {
            int m = wm * 64 + mt * 16 + rG;
            aL[mt] = *(const uint2*)(Ab + m * 2);
            aH[mt] = *(const uint2*)(Ab + (m + 8) * 2);
        }
        #pragma unroll
        for (int nt = 0; nt < 8; nt++) {
            uint2 bb = *(const uint2*)(Bb + (wn * 64 + nt * 8 + rG) * 2);
            #pragma unroll
            for (int mt = 0; mt < 4; mt++)
                mma_f16(acc[mt][nt], aL[mt].x, aH[mt].x, aL[mt].y, aH[mt].y, bb.x, bb.y);
        }
    }
}

// ---------------- GEMM: projections (fp16 MMA, fp16 output) --------------------
__global__ void __launch_bounds__(128, 2) gemm_proj_f16(
    const float* __restrict__ A, const float* __restrict__ W,
    const float* __restrict__ bias, uint32_t* __restrict__ Cout16)
{
    __shared__ uint32_t sm[2 * STAGE_U32];
    int g0 = blockIdx.x * PBM, bn = blockIdx.y;
    int n = g0 / T_DIM, t0 = g0 % T_DIM;
    const float* Aptr = A + (size_t)n * C_DIM * T_DIM + t0;
    const float* Bptr = W + (size_t)(bn * PBN) * C_DIM;

    int tid = threadIdx.x, lane = tid & 31, wid = tid >> 5;
    int wm = wid >> 1, wn = wid & 1, q = lane & 3, rG = lane >> 2;

    float acc[4][8][4];
    #pragma unroll
    for (int a = 0; a < 4; a++)
        #pragma unroll
        for (int b = 0; b < 8; b++)
            #pragma unroll
            for (int c = 0; c < 4; c++) acc[a][b][c] = 0.f;

    LdrAS la;
    LdrKM lb;
    la.ldg(Aptr, 0, tid);
    lb.ldg(Bptr, C_DIM, 0, tid);
    la.sts(sm, tid);
    lb.sts(sm + OPER_U32, tid);
    __syncthreads();

    for (int kt = 0; kt < NKT; kt++) {
        int p = kt & 1;
        if (kt + 1 < NKT) {
            la.ldg(Aptr, kt + 1, tid);
            lb.ldg(Bptr, C_DIM, kt + 1, tid);
        }
        const uint32_t* As = sm + p * STAGE_U32;
        mma_stage16(As, As + OPER_U32, acc, wm, wn, q, rG);
        if (kt + 1 < NKT) {
            uint32_t* d = sm + (p ^ 1) * STAGE_U32;
            la.sts(d, tid);
            lb.sts(d + OPER_U32, tid);
        }
        __syncthreads();
    }

    #pragma unroll
    for (int nt = 0; nt < 8; nt++) {
        int cb = bn * PBN + wn * 64 + nt * 8 + 2 * q;
        float b0 = bias[cb], b1 = bias[cb + 1];
        int wi = cb >> 1;
        #pragma unroll
        for (int mt = 0; mt < 4; mt++) {
            int r = g0 + wm * 64 + mt * 16 + rG;
            Cout16[(size_t)r * C_W + wi]       = pack_f16x2(acc[mt][nt][0] + b0, acc[mt][nt][1] + b1);
            Cout16[(size_t)(r + 8) * C_W + wi] = pack_f16x2(acc[mt][nt][2] + b0, acc[mt][nt][3] + b1);
        }
    }
}

// ---------------- GEMM: out-proj (fp16 A scratch) + bias + mask + residual ------
__global__ void __launch_bounds__(128, 2) gemm_out_f16(
    const float* __restrict__ W, const float* __restrict__ bias,
    const float* __restrict__ masks, const float* __restrict__ x,
    float* __restrict__ out)
{
    __shared__ uint32_t sm[2 * STAGE_U32];
    int g0 = blockIdx.x * PBM, bn = blockIdx.y;
    int n = g0 / T_DIM, t0 = g0 % T_DIM;
    const uint32_t* Aptr = g_AO16 + (size_t)g0 * C_W;
    const float* Bptr = W + (size_t)(bn * PBN) * C_DIM;

    int tid = threadIdx.x, lane = tid & 31, wid = tid >> 5;
    int wm = wid >> 1, wn = wid & 1, q = lane & 3, rG = lane >> 2;

    float acc[4][8][4];
    #pragma unroll
    for (int a = 0; a < 4; a++)
        #pragma unroll
        for (int b = 0; b < 8; b++)
            #pragma unroll
            for (int c = 0; c < 4; c++) acc[a][b][c] = 0.f;

    LdrA16 la;
    LdrKM lb;
    la.ldg(Aptr, 0, tid);
    lb.ldg(Bptr, C_DIM, 0, tid);
    la.sts(sm, tid);
    lb.sts(sm + OPER_U32, tid);
    __syncthreads();

    for (int kt = 0; kt < NKT; kt++) {
        int p = kt & 1;
        if (kt + 1 < NKT) {
            la.ldg(Aptr, kt + 1, tid);
            lb.ldg(Bptr, C_DIM, kt + 1, tid);
        }
        const uint32_t* As = sm + p * STAGE_U32;
        mma_stage16(As, As + OPER_U32, acc, wm, wn, q, rG);
        if (kt + 1 < NKT) {
            uint32_t* d = sm + (p ^ 1) * STAGE_U32;
            la.sts(d, tid);
            lb.sts(d + OPER_U32, tid);
        }
        __syncthreads();
    }

    #pragma unroll
    for (int mt = 0; mt < 4; mt++) {
        int r = wm * 64 + mt * 16 + rG;
        int tA = t0 + r;
        float mkA = masks[(size_t)n * T_DIM + tA];
        float mkB = masks[(size_t)n * T_DIM + tA + 8];
        #pragma unroll
        for (int nt = 0; nt < 8; nt++) {
            int co = bn * PBN + wn * 64 + nt * 8 + 2 * q;
            #pragma unroll
            for (int cj = 0; cj < 2; cj++) {
                float bb = bias[co + cj];
                size_t iA = ((size_t)(n * C_DIM + co + cj)) * T_DIM + tA;
                out[iA]     = (acc[mt][nt][cj]     + bb) * mkA + x[iA];
                out[iA + 8] = (acc[mt][nt][2 + cj] + bb) * mkB + x[iA + 8];
            }
        }
    }
}

// ---------------- attention (fp16 scratch, fp16 MMA) ---------------------------
__global__ void __launch_bounds__(128) attn_f16(const float* __restrict__ masks)
{
    extern __shared__ uint32_t ash[];
    uint32_t* sQ = ash;                 // Q, later reused for P
    uint32_t* sK = ash + ABUF2;
    uint32_t* sV = ash + 2 * ABUF2;     // V^T words: (V[2t][d], V[2t+1][d])
    float* skm   = (float*)(ash + 3 * ABUF2);

    int cb = blockIdx.x, h = blockIdx.y;
    int g0 = cb * CHUNK_SZ;
    int n = g0 / T_DIM, t0 = g0 % T_DIM;
    int tid = threadIdx.x, lane = tid & 31, w = tid >> 5;
    int q = lane & 3, rG = lane >> 2;

    if (tid < 64)
        skm[tid] = (masks[(size_t)n * T_DIM + t0 + tid] > 0.f) ? 0.f : NEG_INF;

    // ---- load Q, K: pre-packed words, pure copy into MMA layout ----
    {
        int m = tid >> 1;
        int kw0 = (tid & 1) * 16;
        const uint32_t* qp = g_QP16 + (size_t)(g0 + m) * C_W + h * 32 + kw0;
        const uint32_t* kp = g_KP16 + (size_t)(g0 + m) * C_W + h * 32 + kw0;
        #pragma unroll
        for (int i = 0; i < 4; i++) {
            int kw4 = kw0 + i * 4;
            int sb = (kw4 >> 3) * 4;
            int kh = (kw4 >> 2) & 1;
            uint4 u = *(const uint4*)(qp + i * 4);
            sQ[((uint32_t)(sb + 0) * AP2 + m) * 2 + kh] = u.x;
            sQ[((uint32_t)(sb + 1) * AP2 + m) * 2 + kh] = u.y;
            sQ[((uint32_t)(sb + 2) * AP2 + m) * 2 + kh] = u.z;
            sQ[((uint32_t)(sb + 3) * AP2 + m) * 2 + kh] = u.w;
            u = *(const uint4*)(kp + i * 4);
            sK[((uint32_t)(sb + 0) * AP2 + m) * 2 + kh] = u.x;
            sK[((uint32_t)(sb + 1) * AP2 + m) * 2 + kh] = u.y;
            sK[((uint32_t)(sb + 2) * AP2 + m) * 2 + kh] = u.z;
            sK[((uint32_t)(sb + 3) * AP2 + m) * 2 + kh] = u.w;
        }
    }
    // ---- load V^T: token-pair transpose via prmt ----
    {
        int tp = tid >> 2;                   // token pair 0..31
        int w0 = (tid & 3) * 8;              // word offset in 32-word head slice
        const uint32_t* r0 = g_VP16 + (size_t)(g0 + 2 * tp) * C_W + h * 32 + w0;
        const uint32_t* r1 = r0 + C_W;
        int slot = (tp >> 3) * 4 + (tp & 3);
        int kh = (tp >> 2) & 1;
        uint32_t* dst = sV + ((uint32_t)slot * AP2 + 2 * w0) * 2 + kh;
        #pragma unroll
        for (int half = 0; half < 2; half++) {
            uint4 a = *(const uint4*)(r0 + half * 4);
            uint4 b = *(const uint4*)(r1 + half * 4);
            const uint32_t* aw = (const uint32_t*)&a;
            const uint32_t* bw = (const uint32_t*)&b;
            #pragma unroll
            for (int j = 0; j < 4; j++) {
                dst[(half * 8 + 2 * j) * 2]     = prmt_u32(aw[j], bw[j], 0x5410);
                dst[(half * 8 + 2 * j + 1) * 2] = prmt_u32(aw[j], bw[j], 0x7632);
            }
        }
    }
    __syncthreads();

    int mA = w * 16 + rG;

    // ---- S = Q K^T ----
    float s[8][4];
    #pragma unroll
    for (int nt = 0; nt < 8; nt++)
        #pragma unroll
        for (int j = 0; j < 4; j++) s[nt][j] = 0.f;
    #pragma unroll
    for (int ks = 0; ks < 4; ks++) {
        const uint32_t* Ab = sQ + ((uint32_t)(ks * 4 + q) * AP2) * 2;
        const uint32_t* Bb = sK + ((uint32_t)(ks * 4 + q) * AP2) * 2;
        uint2 aL = *(const uint2*)(Ab + mA * 2);
        uint2 aH = *(const uint2*)(Ab + (mA + 8) * 2);
        #pragma unroll
        for (int nt = 0; nt < 8; nt++) {
            uint2 bb = *(const uint2*)(Bb + (nt * 8 + rG) * 2);
            mma_f16(s[nt], aL.x, aH.x, aL.y, aH.y, bb.x, bb.y);
        }
    }

    // ---- softmax in registers ----
    const float scale = 0.125f;
    float mxA = -3.4e38f, mxB = -3.4e38f;
    #pragma unroll
    for (int nt = 0; nt < 8; nt++) {
        int c0 = nt * 8 + 2 * q;
        float a0 = skm[c0], a1 = skm[c0 + 1];
        s[nt][0] = s[nt][0] * scale + a0;
        s[nt][1] = s[nt][1] * scale + a1;
        s[nt][2] = s[nt][2] * scale + a0;
        s[nt][3] = s[nt][3] * scale + a1;
        mxA = fmaxf(mxA, fmaxf(s[nt][0], s[nt][1]));
        mxB = fmaxf(mxB, fmaxf(s[nt][2], s[nt][3]));
    }
    mxA = fmaxf(mxA, __shfl_xor_sync(0xffffffffu, mxA, 1));
    mxA = fmaxf(mxA, __shfl_xor_sync(0xffffffffu, mxA, 2));
    mxB = fmaxf(mxB, __shfl_xor_sync(0xffffffffu, mxB, 1));
    mxB = fmaxf(mxB, __shfl_xor_sync(0xffffffffu, mxB, 2));
    float sA = 0.f, sB = 0.f;
    #pragma unroll
    for (int nt = 0; nt < 8; nt++) {
        s[nt][0] = __expf(s[nt][0] - mxA);
        s[nt][1] = __expf(s[nt][1] - mxA);
        s[nt][2] = __expf(s[nt][2] - mxB);
        s[nt][3] = __expf(s[nt][3] - mxB);
        sA += s[nt][0] + s[nt][1];
        sB += s[nt][2] + s[nt][3];
    }
    sA += __shfl_xor_sync(0xffffffffu, sA, 1);
    sA += __shfl_xor_sync(0xffffffffu, sA, 2);
    sB += __shfl_xor_sync(0xffffffffu, sB, 1);
    sB += __shfl_xor_sync(0xffffffffu, sB, 2);
    float iA = 1.f / sA, iB = 1.f / sB;

    // ---- write P into sQ (warp-local rows) ----
    #pragma unroll
    for (int nt = 0; nt < 8; nt++) {
        int kw = nt * 4 + q;
        int slot = (kw >> 3) * 4 + (kw & 3);
        int kh = (kw >> 2) & 1;
        sQ[((uint32_t)slot * AP2 + mA) * 2 + kh]     = pack_f16x2(s[nt][0] * iA, s[nt][1] * iA);
        sQ[((uint32_t)slot * AP2 + mA + 8) * 2 + kh] = pack_f16x2(s[nt][2] * iB, s[nt][3] * iB);
    }
    __syncwarp();

    // ---- O = P V ----
    float o[8][4];
    #pragma unroll
    for (int nt = 0; nt < 8; nt++)
        #pragma unroll
        for (int j = 0; j < 4; j++) o[nt][j] = 0.f;
    #pragma unroll
    for (int ks = 0; ks < 4; ks++) {
        const uint32_t* Ab = sQ + ((uint32_t)(ks * 4 + q) * AP2) * 2;
        const uint32_t* Bb = sV + ((uint32_t)(ks * 4 + q) * AP2) * 2;
        uint2 aL = *(const uint2*)(Ab + mA * 2);
        uint2 aH = *(const uint2*)(Ab + (mA + 8) * 2);
        #pragma unroll
        for (int nt = 0; nt < 8; nt++) {
            uint2 bb = *(const uint2*)(Bb + (nt * 8 + rG) * 2);
            mma_f16(o[nt], aL.x, aH.x, aL.y, aH.y, bb.x, bb.y);
        }
    }

    // ---- store O packed fp16 to g_AO16 ----
    uint32_t* aoA = g_AO16 + (size_t)(g0 + mA) * C_W + h * 32;
    uint32_t* aoB = g_AO16 + (size_t)(g0 + mA + 8) * C_W + h * 32;
    #pragma unroll
    for (int nt = 0; nt < 8; nt++) {
        aoA[nt * 4 + q] = pack_f16x2(o[nt][0], o[nt][1]);
        aoB[nt * 4 + q] = pack_f16x2(o[nt][2], o[nt][3]);
    }
}

// ---------------- InstanceNorm1d over T per (n,c) row ---------------------------
__global__ void __launch_bounds__(256) inorm_kernel(float* __restrict__ out)
{
    __shared__ float red[18];
    int row = blockIdx.x;
    float* p = out + (size_t)row * T_DIM;
    int tid = threadIdx.x;

    float4 v[4];
    float s = 0.f, s2 = 0.f;
    #pragma unroll
    for (int i = 0; i < 4; i++) {
        v[i] = *(const float4*)(p + i * 1024 + tid * 4);
        s  += v[i].x + v[i].y + v[i].z + v[i].w;
        s2 += v[i].x * v[i].x + v[i].y * v[i].y + v[i].z * v[i].z + v[i].w * v[i].w;
    }
    #pragma unroll
    for (int o = 16; o; o >>= 1) {
        s  += __shfl_xor_sync(0xffffffffu, s,  o);
        s2 += __shfl_xor_sync(0xffffffffu, s2, o);
    }
    int warp = tid >> 5, lane = tid & 31;
    if (lane == 0) { red[warp] = s; red[8 + warp] = s2; }
    __syncthreads();
    if (warp == 0) {
        float a  = (lane < 8) ? red[lane]     : 0.f;
        float a2 = (lane < 8) ? red[8 + lane] : 0.f;
        #pragma unroll
        for (int o = 4; o; o >>= 1) {
            a  += __shfl_xor_sync(0xffffffffu, a,  o);
            a2 += __shfl_xor_sync(0xffffffffu, a2, o);
        }
        if (lane == 0) { red[16] = a; red[17] = a2; }
    }
    __syncthreads();
    float mu  = red[16] * (1.f / T_DIM);
    float var = red[17] * (1.f / T_DIM) - mu * mu;
    float rs  = rsqrtf(var + 1e-5f);
    #pragma unroll
    for (int i = 0; i < 4; i++) {
        float4 r;
        r.x = (v[i].x - mu) * rs; r.y = (v[i].y - mu) * rs;
        r.z = (v[i].z - mu) * rs; r.w = (v[i].w - mu) * rs;
        *(float4*)(p + i * 1024 + tid * 4) = r;
    }
}

// ---------------- launch ---------------------------------------------------------
extern "C" void kernel_launch(void* const* d_in, const int* in_sizes, int n_in,
                              void* d_out, int out_size)
{
    const float* x     = (const float*)d_in[0];
    const float* q     = (const float*)d_in[1];
    const float* k     = (const float*)d_in[2];
    const float* v     = (const float*)d_in[3];
    const float* masks = (const float*)d_in[4];
    const float* W_in  = (const float*)d_in[5];
    const float* b_in  = (const float*)d_in[6];
    const float* W_out = (const float*)d_in[7];
    const float* b_out = (const float*)d_in[8];
    float* out = (float*)d_out;

    uint32_t *QP, *KP, *VP;
    cudaGetSymbolAddress((void**)&QP, g_QP16);
    cudaGetSymbolAddress((void**)&KP, g_KP16);
    cudaGetSymbolAddress((void**)&VP, g_VP16);

    cudaFuncSetAttribute(attn_f16, cudaFuncAttributeMaxDynamicSharedMemorySize,
                         ASMEM2);

    dim3 gg(NTOK / PBM, C_DIM / PBN);   // (128, 4)
    gemm_proj_f16<<<gg, 128>>>(q, W_in,                         b_in,        QP);
    gemm_proj_f16<<<gg, 128>>>(k, W_in + (size_t)512  * C_DIM,  b_in + 512,  KP);
    gemm_proj_f16<<<gg, 128>>>(v, W_in + (size_t)1024 * C_DIM,  b_in + 1024, VP);

    attn_f16<<<dim3(NTOK / CHUNK_SZ, H_HEADS), 128, ASMEM2>>>(masks);

    gemm_out_f16<<<gg, 128>>>(W_out, b_out, masks, x, out);

    inorm_kernel<<<N_BATCH * C_DIM, 256>>>(out);
}

// round 8
// speedup vs baseline: 4.3873x; 1.0364x over previous
#include <cuda_runtime.h>
#include <cuda_bf16.h>
#include <cstdint>

#define N_BATCH 4
#define C_DIM   512
#define C_W     256            // C_DIM/2 f16x2 words per row
#define T_DIM   4096
#define NTOK    (N_BATCH * T_DIM)   // 16384
#define H_HEADS 8
#define DH      64
#define CHUNK_SZ 64
#define NEG_INF (-1e9f)

// ---------------- fp16 GEMM tiling (ldmatrix + cp.async) ----------------------
#define PBM 128
#define PBN 128
#define NKT (C_DIM / 32)       // 16 k-tiles of 32
#define WPITCH 20              // u32 per smem row: 16 data + 4 pad (80 B, odd*16B)
#define TILE_U32 (128 * WPITCH)        // 2560
#define STAGE32 (2 * TILE_U32)         // A+B one stage: 5120 u32 (20 KB)

// ---------------- fp16 attention tiling ---------------------------------------
#define AP2 68
#define ABUF2 (16 * AP2 * 2)
#define ASMEM2 ((3 * ABUF2 + 64) * 4)

// ---------------- scratch (fp16 packed as u32 words) ---------------------------
__device__ __align__(16) uint32_t g_QP16[(size_t)NTOK * C_W];
__device__ __align__(16) uint32_t g_KP16[(size_t)NTOK * C_W];
__device__ __align__(16) uint32_t g_VP16[(size_t)NTOK * C_W];
__device__ __align__(16) uint32_t g_AO16[(size_t)NTOK * C_W];
__device__ __align__(16) uint32_t g_W16[(size_t)2048 * C_W];   // rows 0-1535 Win, 1536-2047 Wout

// ---------------- helpers ------------------------------------------------------
__device__ __forceinline__ uint32_t pack_f16x2(float lo, float hi) {
    uint32_t r;
    asm("cvt.rn.f16x2.f32 %0, %1, %2;" : "=r"(r) : "f"(hi), "f"(lo));
    return r;
}

__device__ __forceinline__ uint32_t prmt_u32(uint32_t a, uint32_t b, uint32_t sel) {
    uint32_t r;
    asm("prmt.b32 %0, %1, %2, %3;" : "=r"(r) : "r"(a), "r"(b), "r"(sel));
    return r;
}

__device__ __forceinline__ void mma_f16(float* c,
                                        uint32_t a0, uint32_t a1, uint32_t a2, uint32_t a3,
                                        uint32_t b0, uint32_t b1) {
    asm volatile(
        "mma.sync.aligned.m16n8k16.row.col.f32.f16.f16.f32 "
        "{%0,%1,%2,%3}, {%4,%5,%6,%7}, {%8,%9}, {%0,%1,%2,%3};\n"
        : "+f"(c[0]), "+f"(c[1]), "+f"(c[2]), "+f"(c[3])
        : "r"(a0), "r"(a1), "r"(a2), "r"(a3), "r"(b0), "r"(b1));
}

__device__ __forceinline__ void ldsm_x4(uint32_t& r0, uint32_t& r1, uint32_t& r2,
                                        uint32_t& r3, uint32_t addr) {
    asm volatile("ldmatrix.sync.aligned.m8n8.x4.shared.b16 {%0,%1,%2,%3}, [%4];"
                 : "=r"(r0), "=r"(r1), "=r"(r2), "=r"(r3) : "r"(addr));
}

#define CP_ASYNC16(dst, src) \
    asm volatile("cp.async.cg.shared.global [%0], [%1], 16;" :: "r"(dst), "l"(src))
#define CP_COMMIT() asm volatile("cp.async.commit_group;")
#define CP_WAIT0()  asm volatile("cp.async.wait_group 0;" ::: "memory")

// mma over one smem stage: A tile rows m (128x32 f16), B tile rows n; row-major, pitch 80B
__device__ __forceinline__ void mma_tile_f16(uint32_t sA, uint32_t sB,
                                             float acc[4][8][4],
                                             int wm, int wn, int lane) {
    int rA = wm * 64 + (lane & 7) + ((lane >> 3) & 1) * 8;   // + mt*16
    int cA = ((lane >> 4) & 1) * 16;
    int rB = wn * 64 + (lane & 7) + ((lane >> 4) & 1) * 8;   // + nt2*16
    int cB = ((lane >> 3) & 1) * 16;
    #pragma unroll
    for (int ks = 0; ks < 2; ks++) {
        uint32_t a[4][4], b[4][4];
        #pragma unroll
        for (int mt = 0; mt < 4; mt++)
            ldsm_x4(a[mt][0], a[mt][1], a[mt][2], a[mt][3],
                    sA + (uint32_t)(rA + mt * 16) * 80 + cA + ks * 32);
        #pragma unroll
        for (int nt2 = 0; nt2 < 4; nt2++)
            ldsm_x4(b[nt2][0], b[nt2][1], b[nt2][2], b[nt2][3],
                    sB + (uint32_t)(rB + nt2 * 16) * 80 + cB + ks * 32);
        #pragma unroll
        for (int mt = 0; mt < 4; mt++)
            #pragma unroll
            for (int nt2 = 0; nt2 < 4; nt2++) {
                mma_f16(acc[mt][2 * nt2],     a[mt][0], a[mt][1], a[mt][2], a[mt][3],
                        b[nt2][0], b[nt2][1]);
                mma_f16(acc[mt][2 * nt2 + 1], a[mt][0], a[mt][1], a[mt][2], a[mt][3],
                        b[nt2][2], b[nt2][3]);
            }
    }
}

// ---------------- weight pre-pack ----------------------------------------------
__global__ void pack_weights(const float* __restrict__ Win, const float* __restrict__ Wout)
{
    int i = blockIdx.x * 256 + threadIdx.x;          // word index, 2048*256 total
    int row = i >> 8, kw = i & 255;
    const float* src = (row < 1536) ? (Win + (size_t)row * C_DIM + 2 * kw)
                                    : (Wout + (size_t)(row - 1536) * C_DIM + 2 * kw);
    float2 f = *(const float2*)src;
    g_W16[i] = pack_f16x2(f.x, f.y);
}

// ---------------- GEMM: 3 projections in one launch (z = q/k/v) -----------------
__global__ void __launch_bounds__(128, 2) gemm_proj_v2(
    const float* __restrict__ qin, const float* __restrict__ kin,
    const float* __restrict__ vin, const float* __restrict__ b_in)
{
    __shared__ __align__(16) uint32_t sm[2 * STAGE32];
    int z = blockIdx.z;
    const float* A = (z == 0) ? qin : (z == 1) ? kin : vin;
    uint32_t* Cout16 = (z == 0) ? g_QP16 : (z == 1) ? g_KP16 : g_VP16;
    const float* bias = b_in + z * C_DIM;

    int g0 = blockIdx.x * PBM, bn = blockIdx.y;
    int n = g0 / T_DIM, t0 = g0 % T_DIM;
    const float* Abase = A + (size_t)n * C_DIM * T_DIM + t0;
    const uint32_t* Wb = g_W16 + (size_t)(z * 512 + bn * PBN) * C_W;

    int tid = threadIdx.x, lane = tid & 31, wid = tid >> 5;
    int wm = wid >> 1, wn = wid & 1, q2 = lane & 3, rG = lane >> 2;
    uint32_t sbase = (uint32_t)__cvta_generic_to_shared(sm);

    float acc[4][8][4];
    #pragma unroll
    for (int a = 0; a < 4; a++)
        #pragma unroll
        for (int b = 0; b < 8; b++)
            #pragma unroll
            for (int c = 0; c < 4; c++) acc[a][b][c] = 0.f;

    int m0 = (tid & 31) * 4, kw0 = (tid >> 5) * 4;
    float4 av[8];

    // prologue: stage 0
    {
        int c0 = 2 * kw0;
        #pragma unroll
        for (int cr = 0; cr < 8; cr++)
            av[cr] = *(const float4*)(Abase + (size_t)(c0 + cr) * T_DIM + m0);
        uint32_t d = sbase + TILE_U32 * 4 + tid * 80;
        const uint32_t* s = Wb + (size_t)tid * C_W;
        #pragma unroll
        for (int ch = 0; ch < 4; ch++) CP_ASYNC16(d + ch * 16, s + ch * 4);
        CP_COMMIT();
        const float* fv = (const float*)av;
        #pragma unroll
        for (int i = 0; i < 4; i++) {
            uint4 u;
            u.x = pack_f16x2(fv[0 + i],  fv[4 + i]);
            u.y = pack_f16x2(fv[8 + i],  fv[12 + i]);
            u.z = pack_f16x2(fv[16 + i], fv[20 + i]);
            u.w = pack_f16x2(fv[24 + i], fv[28 + i]);
            *(uint4*)(sm + (m0 + i) * WPITCH + kw0) = u;
        }
    }
    CP_WAIT0();
    __syncthreads();

    for (int kt = 0; kt < NKT; kt++) {
        int p = kt & 1;
        if (kt + 1 < NKT) {
            int c0 = (kt + 1) * 32 + 2 * kw0;
            #pragma unroll
            for (int cr = 0; cr < 8; cr++)
                av[cr] = *(const float4*)(Abase + (size_t)(c0 + cr) * T_DIM + m0);
            uint32_t d = sbase + ((p ^ 1) * STAGE32 + TILE_U32) * 4 + tid * 80;
            const uint32_t* s = Wb + (size_t)tid * C_W + (kt + 1) * 16;
            #pragma unroll
            for (int ch = 0; ch < 4; ch++) CP_ASYNC16(d + ch * 16, s + ch * 4);
            CP_COMMIT();
        }
        mma_tile_f16(sbase + p * STAGE32 * 4, sbase + (p * STAGE32 + TILE_U32) * 4,
                     acc, wm, wn, lane);
        if (kt + 1 < NKT) {
            uint32_t* buf = sm + (p ^ 1) * STAGE32;
            const float* fv = (const float*)av;
            #pragma unroll
            for (int i = 0; i < 4; i++) {
                uint4 u;
                u.x = pack_f16x2(fv[0 + i],  fv[4 + i]);
                u.y = pack_f16x2(fv[8 + i],  fv[12 + i]);
                u.z = pack_f16x2(fv[16 + i], fv[20 + i]);
                u.w = pack_f16x2(fv[24 + i], fv[28 + i]);
                *(uint4*)(buf + (m0 + i) * WPITCH + kw0) = u;
            }
            CP_WAIT0();
        }
        __syncthreads();
    }

    // epilogue: packed fp16 output [g][cw]
    #pragma unroll
    for (int nt = 0; nt < 8; nt++) {
        int cb = bn * PBN + wn * 64 + nt * 8 + 2 * q2;
        float b0 = bias[cb], b1 = bias[cb + 1];
        int wi = cb >> 1;
        #pragma unroll
        for (int mt = 0; mt < 4; mt++) {
            int r = g0 + wm * 64 + mt * 16 + rG;
            Cout16[(size_t)r * C_W + wi]       = pack_f16x2(acc[mt][nt][0] + b0, acc[mt][nt][1] + b1);
            Cout16[(size_t)(r + 8) * C_W + wi] = pack_f16x2(acc[mt][nt][2] + b0, acc[mt][nt][3] + b1);
        }
    }
}

// ---------------- GEMM: out-proj (A & B cp.async) + bias + mask + residual ------
__global__ void __launch_bounds__(128, 2) gemm_out_v2(
    const float* __restrict__ bias, const float* __restrict__ masks,
    const float* __restrict__ x, float* __restrict__ out)
{
    __shared__ __align__(16) uint32_t sm[2 * STAGE32];
    int g0 = blockIdx.x * PBM, bn = blockIdx.y;
    int n = g0 / T_DIM, t0 = g0 % T_DIM;
    const uint32_t* Ab = g_AO16 + (size_t)g0 * C_W;
    const uint32_t* Wb = g_W16 + (size_t)(1536 + bn * PBN) * C_W;

    int tid = threadIdx.x, lane = tid & 31, wid = tid >> 5;
    int wm = wid >> 1, wn = wid & 1, q2 = lane & 3, rG = lane >> 2;
    uint32_t sbase = (uint32_t)__cvta_generic_to_shared(sm);

    float acc[4][8][4];
    #pragma unroll
    for (int a = 0; a < 4; a++)
        #pragma unroll
        for (int b = 0; b < 8; b++)
            #pragma unroll
            for (int c = 0; c < 4; c++) acc[a][b][c] = 0.f;

    // prologue
    {
        uint32_t dA = sbase + tid * 80;
        uint32_t dB = sbase + TILE_U32 * 4 + tid * 80;
        const uint32_t* sA = Ab + (size_t)tid * C_W;
        const uint32_t* sB = Wb + (size_t)tid * C_W;
        #pragma unroll
        for (int ch = 0; ch < 4; ch++) {
            CP_ASYNC16(dA + ch * 16, sA + ch * 4);
            CP_ASYNC16(dB + ch * 16, sB + ch * 4);
        }
        CP_COMMIT();
    }
    CP_WAIT0();
    __syncthreads();

    for (int kt = 0; kt < NKT; kt++) {
        int p = kt & 1;
        if (kt + 1 < NKT) {
            uint32_t dA = sbase + (p ^ 1) * STAGE32 * 4 + tid * 80;
            uint32_t dB = dA + TILE_U32 * 4;
            const uint32_t* sA = Ab + (size_t)tid * C_W + (kt + 1) * 16;
            const uint32_t* sB = Wb + (size_t)tid * C_W + (kt + 1) * 16;
            #pragma unroll
            for (int ch = 0; ch < 4; ch++) {
                CP_ASYNC16(dA + ch * 16, sA + ch * 4);
                CP_ASYNC16(dB + ch * 16, sB + ch * 4);
            }
            CP_COMMIT();
        }
        mma_tile_f16(sbase + p * STAGE32 * 4, sbase + (p * STAGE32 + TILE_U32) * 4,
                     acc, wm, wn, lane);
        if (kt + 1 < NKT) CP_WAIT0();
        __syncthreads();
    }

    // epilogue: channel-major + mask + residual
    #pragma unroll
    for (int mt = 0; mt < 4; mt++) {
        int r = wm * 64 + mt * 16 + rG;
        int tA = t0 + r;
        float mkA = masks[(size_t)n * T_DIM + tA];
        float mkB = masks[(size_t)n * T_DIM + tA + 8];
        #pragma unroll
        for (int nt = 0; nt < 8; nt++) {
            int co = bn * PBN + wn * 64 + nt * 8 + 2 * q2;
            #pragma unroll
            for (int cj = 0; cj < 2; cj++) {
                float bb = bias[co + cj];
                size_t iA = ((size_t)(n * C_DIM + co + cj)) * T_DIM + tA;
                out[iA]     = (acc[mt][nt][cj]     + bb) * mkA + x[iA];
                out[iA + 8] = (acc[mt][nt][2 + cj] + bb) * mkB + x[iA + 8];
            }
        }
    }
}

// ---------------- attention (fp16 scratch, fp16 MMA) ---------------------------
__global__ void __launch_bounds__(128) attn_f16(const float* __restrict__ masks)
{
    extern __shared__ uint32_t ash[];
    uint32_t* sQ = ash;
    uint32_t* sK = ash + ABUF2;
    uint32_t* sV = ash + 2 * ABUF2;
    float* skm   = (float*)(ash + 3 * ABUF2);

    int cb = blockIdx.x, h = blockIdx.y;
    int g0 = cb * CHUNK_SZ;
    int n = g0 / T_DIM, t0 = g0 % T_DIM;
    int tid = threadIdx.x, lane = tid & 31, w = tid >> 5;
    int q = lane & 3, rG = lane >> 2;

    if (tid < 64)
        skm[tid] = (masks[(size_t)n * T_DIM + t0 + tid] > 0.f) ? 0.f : NEG_INF;

    {
        int m = tid >> 1;
        int kw0 = (tid & 1) * 16;
        const uint32_t* qp = g_QP16 + (size_t)(g0 + m) * C_W + h * 32 + kw0;
        const uint32_t* kp = g_KP16 + (size_t)(g0 + m) * C_W + h * 32 + kw0;
        #pragma unroll
        for (int i = 0; i < 4; i++) {
            int kw4 = kw0 + i * 4;
            int sb = (kw4 >> 3) * 4;
            int kh = (kw4 >> 2) & 1;
            uint4 u = *(const uint4*)(qp + i * 4);
            sQ[((uint32_t)(sb + 0) * AP2 + m) * 2 + kh] = u.x;
            sQ[((uint32_t)(sb + 1) * AP2 + m) * 2 + kh] = u.y;
            sQ[((uint32_t)(sb + 2) * AP2 + m) * 2 + kh] = u.z;
            sQ[((uint32_t)(sb + 3) * AP2 + m) * 2 + kh] = u.w;
            u = *(const uint4*)(kp + i * 4);
            sK[((uint32_t)(sb + 0) * AP2 + m) * 2 + kh] = u.x;
            sK[((uint32_t)(sb + 1) * AP2 + m) * 2 + kh] = u.y;
            sK[((uint32_t)(sb + 2) * AP2 + m) * 2 + kh] = u.z;
            sK[((uint32_t)(sb + 3) * AP2 + m) * 2 + kh] = u.w;
        }
    }
    {
        int tp = tid >> 2;
        int w0 = (tid & 3) * 8;
        const uint32_t* r0 = g_VP16 + (size_t)(g0 + 2 * tp) * C_W + h * 32 + w0;
        const uint32_t* r1 = r0 + C_W;
        int slot = (tp >> 3) * 4 + (tp & 3);
        int kh = (tp >> 2) & 1;
        uint32_t* dst = sV + ((uint32_t)slot * AP2 + 2 * w0) * 2 + kh;
        #pragma unroll
        for (int half = 0; half < 2; half++) {
            uint4 a = *(const uint4*)(r0 + half * 4);
            uint4 b = *(const uint4*)(r1 + half * 4);
            const uint32_t* aw = (const uint32_t*)&a;
            const uint32_t* bw = (const uint32_t*)&b;
            #pragma unroll
            for (int j = 0; j < 4; j++) {
                dst[(half * 8 + 2 * j) * 2]     = prmt_u32(aw[j], bw[j], 0x5410);
                dst[(half * 8 + 2 * j + 1) * 2] = prmt_u32(aw[j], bw[j], 0x7632);
            }
        }
    }
    __syncthreads();

    int mA = w * 16 + rG;

    float s[8][4];
    #pragma unroll
    for (int nt = 0; nt < 8; nt++)
        #pragma unroll
        for (int j = 0; j < 4; j++) s[nt][j] = 0.f;
    #pragma unroll
    for (int ks = 0; ks < 4; ks++) {
        const uint32_t* Ab = sQ + ((uint32_t)(ks * 4 + q) * AP2) * 2;
        const uint32_t* Bb = sK + ((uint32_t)(ks * 4 + q) * AP2) * 2;
        uint2 aL = *(const uint2*)(Ab + mA * 2);
        uint2 aH = *(const uint2*)(Ab + (mA + 8) * 2);
        #pragma unroll
        for (int nt = 0; nt < 8; nt++) {
            uint2 bb = *(const uint2*)(Bb + (nt * 8 + rG) * 2);
            mma_f16(s[nt], aL.x, aH.x, aL.y, aH.y, bb.x, bb.y);
        }
    }

    const float scale = 0.125f;
    float mxA = -3.4e38f, mxB = -3.4e38f;
    #pragma unroll
    for (int nt = 0; nt < 8; nt++) {
        int c0 = nt * 8 + 2 * q;
        float a0 = skm[c0], a1 = skm[c0 + 1];
        s[nt][0] = s[nt][0] * scale + a0;
        s[nt][1] = s[nt][1] * scale + a1;
        s[nt][2] = s[nt][2] * scale + a0;
        s[nt][3] = s[nt][3] * scale + a1;
        mxA = fmaxf(mxA, fmaxf(s[nt][0], s[nt][1]));
        mxB = fmaxf(mxB, fmaxf(s[nt][2], s[nt][3]));
    }
    mxA = fmaxf(mxA, __shfl_xor_sync(0xffffffffu, mxA, 1));
    mxA = fmaxf(mxA, __shfl_xor_sync(0xffffffffu, mxA, 2));
    mxB = fmaxf(mxB, __shfl_xor_sync(0xffffffffu, mxB, 1));
    mxB = fmaxf(mxB, __shfl_xor_sync(0xffffffffu, mxB, 2));
    float sA = 0.f, sB = 0.f;
    #pragma unroll
    for (int nt = 0; nt < 8; nt++) {
        s[nt][0] = __expf(s[nt][0] - mxA);
        s[nt][1] = __expf(s[nt][1] - mxA);
        s[nt][2] = __expf(s[nt][2] - mxB);
        s[nt][3] = __expf(s[nt][3] - mxB);
        sA += s[nt][0] + s[nt][1];
        sB += s[nt][2] + s[nt][3];
    }
    sA += __shfl_xor_sync(0xffffffffu, sA, 1);
    sA += __shfl_xor_sync(0xffffffffu, sA, 2);
    sB += __shfl_xor_sync(0xffffffffu, sB, 1);
    sB += __shfl_xor_sync(0xffffffffu, sB, 2);
    float iA = 1.f / sA, iB = 1.f / sB;

    #pragma unroll
    for (int nt = 0; nt < 8; nt++) {
        int kw = nt * 4 + q;
        int slot = (kw >> 3) * 4 + (kw & 3);
        int kh = (kw >> 2) & 1;
        sQ[((uint32_t)slot * AP2 + mA) * 2 + kh]     = pack_f16x2(s[nt][0] * iA, s[nt][1] * iA);
        sQ[((uint32_t)slot * AP2 + mA + 8) * 2 + kh] = pack_f16x2(s[nt][2] * iB, s[nt][3] * iB);
    }
    __syncwarp();

    float o[8][4];
    #pragma unroll
    for (int nt = 0; nt < 8; nt++)
        #pragma unroll
        for (int j = 0; j < 4; j++) o[nt][j] = 0.f;
    #pragma unroll
    for (int ks = 0; ks < 4; ks++) {
        const uint32_t* Ab = sQ + ((uint32_t)(ks * 4 + q) * AP2) * 2;
        const uint32_t* Bb = sV + ((uint32_t)(ks * 4 + q) * AP2) * 2;
        uint2 aL = *(const uint2*)(Ab + mA * 2);
        uint2 aH = *(const uint2*)(Ab + (mA + 8) * 2);
        #pragma unroll
        for (int nt = 0; nt < 8; nt++) {
            uint2 bb = *(const uint2*)(Bb + (nt * 8 + rG) * 2);
            mma_f16(o[nt], aL.x, aH.x, aL.y, aH.y, bb.x, bb.y);
        }
    }

    uint32_t* aoA = g_AO16 + (size_t)(g0 + mA) * C_W + h * 32;
    uint32_t* aoB = g_AO16 + (size_t)(g0 + mA + 8) * C_W + h * 32;
    #pragma unroll
    for (int nt = 0; nt < 8; nt++) {
        aoA[nt * 4 + q] = pack_f16x2(o[nt][0], o[nt][1]);
        aoB[nt * 4 + q] = pack_f16x2(o[nt][2], o[nt][3]);
    }
}

// ---------------- InstanceNorm1d over T per (n,c) row ---------------------------
__global__ void __launch_bounds__(256) inorm_kernel(float* __restrict__ out)
{
    __shared__ float red[18];
    int row = blockIdx.x;
    float* p = out + (size_t)row * T_DIM;
    int tid = threadIdx.x;

    float4 v[4];
    float s = 0.f, s2 = 0.f;
    #pragma unroll
    for (int i = 0; i < 4; i++) {
        v[i] = *(const float4*)(p + i * 1024 + tid * 4);
        s  += v[i].x + v[i].y + v[i].z + v[i].w;
        s2 += v[i].x * v[i].x + v[i].y * v[i].y + v[i].z * v[i].z + v[i].w * v[i].w;
    }
    #pragma unroll
    for (int o = 16; o; o >>= 1) {
        s  += __shfl_xor_sync(0xffffffffu, s,  o);
        s2 += __shfl_xor_sync(0xffffffffu, s2, o);
    }
    int warp = tid >> 5, lane = tid & 31;
    if (lane == 0) { red[warp] = s; red[8 + warp] = s2; }
    __syncthreads();
    if (warp == 0) {
        float a  = (lane < 8) ? red[lane]     : 0.f;
        float a2 = (lane < 8) ? red[8 + lane] : 0.f;
        #pragma unroll
        for (int o = 4; o; o >>= 1) {
            a  += __shfl_xor_sync(0xffffffffu, a,  o);
            a2 += __shfl_xor_sync(0xffffffffu, a2, o);
        }
        if (lane == 0) { red[16] = a; red[17] = a2; }
    }
    __syncthreads();
    float mu  = red[16] * (1.f / T_DIM);
    float var = red[17] * (1.f / T_DIM) - mu * mu;
    float rs  = rsqrtf(var + 1e-5f);
    #pragma unroll
    for (int i = 0; i < 4; i++) {
        float4 r;
        r.x = (v[i].x - mu) * rs; r.y = (v[i].y - mu) * rs;
        r.z = (v[i].z - mu) * rs; r.w = (v[i].w - mu) * rs;
        *(float4*)(p + i * 1024 + tid * 4) = r;
    }
}

// ---------------- launch ---------------------------------------------------------
extern "C" void kernel_launch(void* const* d_in, const int* in_sizes, int n_in,
                              void* d_out, int out_size)
{
    const float* x     = (const float*)d_in[0];
    const float* q     = (const float*)d_in[1];
    const float* k     = (const float*)d_in[2];
    const float* v     = (const float*)d_in[3];
    const float* masks = (const float*)d_in[4];
    const float* W_in  = (const float*)d_in[5];
    const float* b_in  = (const float*)d_in[6];
    const float* W_out = (const float*)d_in[7];
    const float* b_out = (const float*)d_in[8];
    float* out = (float*)d_out;

    cudaFuncSetAttribute(attn_f16, cudaFuncAttributeMaxDynamicSharedMemorySize,
                         ASMEM2);

    pack_weights<<<2048, 256>>>(W_in, W_out);

    dim3 gp(NTOK / PBM, C_DIM / PBN, 3);   // (128, 4, 3)
    gemm_proj_v2<<<gp, 128>>>(q, k, v, b_in);

    attn_f16<<<dim3(NTOK / CHUNK_SZ, H_HEADS), 128, ASMEM2>>>(masks);

    dim3 gg(NTOK / PBM, C_DIM / PBN);      // (128, 4)
    gemm_out_v2<<<gg, 128>>>(b_out, masks, x, out);

    inorm_kernel<<<N_BATCH * C_DIM, 256>>>(out);
}